// round 3
// baseline (speedup 1.0000x reference)
#include <cuda_runtime.h>
#include <math.h>

#define B 32
#define S 64
#define T 64
#define E 512
#define H 512
#define V 32000
#define G3 1536   // 3*H

#define ENC_BLOCKS 128
#define DEC_BLOCKS 128

// ---------------- scratch (static device allocations; allowed) ----------------
__device__ float g_esrc[B * S * E];
__device__ float g_etgt[B * T * E];
__device__ float g_gxf[B * S * G3];
__device__ float g_gxb[B * S * G3];
__device__ float g_gxemb[B * T * G3];
__device__ float g_srchid[B * S * 2 * H];    // [b,s,2H]
__device__ float g_Uh[B * S * H];
__device__ float g_hTf[2][H * B];            // packed float4 layout: idx=(k4*B+b)*4+c
__device__ float g_hTb[2][H * B];
__device__ float g_hTd[2][H * B];
__device__ float g_ghd[G3 * B];              // [j][b]
__device__ float g_Ah[B * H];                // [b][k]
__device__ float g_escore[B * S];
__device__ float g_cT[2 * H * B];            // packed float4 [k4][b]
__device__ float g_decout[B * T * H];
__device__ float g_logits[(size_t)B * T * V];
__device__ float g_rowres[B * T];

// grid barrier state
__device__ volatile unsigned g_gen;
__device__ unsigned g_cnt;

__device__ __forceinline__ float sigm(float x) { return 1.0f / (1.0f + expf(-x)); }
__device__ __forceinline__ float tanh_fast(float x) {
    float y; asm("tanh.approx.f32 %0, %1;" : "=f"(y) : "f"(x)); return y;
}

__device__ __forceinline__ void grid_sync(unsigned nb) {
    __syncthreads();
    if (threadIdx.x == 0) {
        unsigned gen = g_gen;
        __threadfence();
        if (atomicAdd(&g_cnt, 1u) == nb - 1) {
            g_cnt = 0;
            __threadfence();
            g_gen = gen + 1;
        } else {
            while (g_gen == gen) { }
        }
        __threadfence();
    }
    __syncthreads();
}

// ---------------- init ----------------
__global__ void zero_h_kernel() {
    int idx = blockIdx.x * blockDim.x + threadIdx.x;
    if (idx < H * B) {
        g_hTf[0][idx] = 0.f; g_hTb[0][idx] = 0.f; g_hTd[0][idx] = 0.f;
    }
    if (idx == 0) { g_cnt = 0; g_gen = 0; }
}

// ---------------- embedding gather ----------------
__global__ __launch_bounds__(128) void embed_kernel(
    const int* __restrict__ src_seqs, const int* __restrict__ tgt_seqs,
    const float* __restrict__ src_emb, const float* __restrict__ tgt_emb)
{
    int blk = blockIdx.x;
    int tid = threadIdx.x;
    if (blk < B * S) {
        int tok = src_seqs[blk];
        const float4* s = (const float4*)(src_emb + (size_t)tok * E);
        float4* d = (float4*)(g_esrc + (size_t)blk * E);
        d[tid] = s[tid];
    } else {
        int r = blk - B * S;
        int tok = tgt_seqs[r];
        const float4* s = (const float4*)(tgt_emb + (size_t)tok * E);
        float4* d = (float4*)(g_etgt + (size_t)r * E);
        d[tid] = s[tid];
    }
}

// ---------------- generic fp32 GEMM: C[M,N] = A[M,K] @ W[N,K]^T + bias ----------------
#define GBM 128
#define GBN 64
#define GBK 16
__global__ __launch_bounds__(256) void gemm_nt(
    const float* __restrict__ A, int lda,
    const float* __restrict__ W, int ldw,
    const float* __restrict__ bias,
    float* __restrict__ C, int ldc, int K)
{
    __shared__ float As[GBK][GBM];
    __shared__ float Bs[GBK][GBN];
    int tid = threadIdx.x;
    int m0 = blockIdx.y * GBM;
    int n0 = blockIdx.x * GBN;
    int tx = tid & 15, ty = tid >> 4;

    float acc[8][4];
#pragma unroll
    for (int i = 0; i < 8; i++)
#pragma unroll
        for (int j = 0; j < 4; j++) acc[i][j] = 0.f;

    int ar0 = tid >> 2;
    int ak0 = (tid & 3) * 4;
    int bn = tid >> 2;
    int bk0 = (tid & 3) * 4;

    for (int k0 = 0; k0 < K; k0 += GBK) {
#pragma unroll
        for (int h = 0; h < 2; h++) {
            int r = ar0 + h * 64;
            float4 v = *(const float4*)(A + (size_t)(m0 + r) * lda + k0 + ak0);
            As[ak0 + 0][r] = v.x; As[ak0 + 1][r] = v.y;
            As[ak0 + 2][r] = v.z; As[ak0 + 3][r] = v.w;
        }
        {
            float4 v = *(const float4*)(W + (size_t)(n0 + bn) * ldw + k0 + bk0);
            Bs[bk0 + 0][bn] = v.x; Bs[bk0 + 1][bn] = v.y;
            Bs[bk0 + 2][bn] = v.z; Bs[bk0 + 3][bn] = v.w;
        }
        __syncthreads();
#pragma unroll
        for (int kk = 0; kk < GBK; kk++) {
            float a[8], b[4];
#pragma unroll
            for (int i = 0; i < 8; i++) a[i] = As[kk][ty * 8 + i];
#pragma unroll
            for (int j = 0; j < 4; j++) b[j] = Bs[kk][tx * 4 + j];
#pragma unroll
            for (int i = 0; i < 8; i++)
#pragma unroll
                for (int j = 0; j < 4; j++) acc[i][j] = fmaf(a[i], b[j], acc[i][j]);
        }
        __syncthreads();
    }
    float b4[4];
#pragma unroll
    for (int j = 0; j < 4; j++) b4[j] = bias[n0 + tx * 4 + j];
#pragma unroll
    for (int i = 0; i < 8; i++) {
        int m = m0 + ty * 8 + i;
        float4 o;
        o.x = acc[i][0] + b4[0]; o.y = acc[i][1] + b4[1];
        o.z = acc[i][2] + b4[2]; o.w = acc[i][3] + b4[3];
        *(float4*)(C + (size_t)m * ldc + n0 + tx * 4) = o;
    }
}

// ---------------- persistent encoder: all S steps, grid-sync between ----------------
__global__ __launch_bounds__(128) void enc_persist(
    const float* __restrict__ Whh_f, const float* __restrict__ bhh_f,
    const float* __restrict__ Whh_b, const float* __restrict__ bhh_b,
    const int* __restrict__ src_lengths)
{
    int lane = threadIdx.x & 31;           // = b
    int w = threadIdx.x >> 5;
    int bx = blockIdx.x;
    int dir = bx >> 6;
    int j0 = (bx & 63) * 8 + w * 2;        // thread handles j0, j0+1
    const float* gx = dir ? g_gxb : g_gxf;
    const float* Whh = dir ? Whh_b : Whh_f;
    const float* bhh = dir ? bhh_b : bhh_f;
    float* hbuf0 = dir ? g_hTb[0] : g_hTf[0];
    float* hbuf1 = dir ? g_hTb[1] : g_hTf[1];
    int len = src_lengths[lane];

    const float* wr = Whh + (size_t)j0 * H;
    const float* wz = Whh + (size_t)(H + j0) * H;
    const float* wn = Whh + (size_t)(2 * H + j0) * H;
    float br0 = bhh[j0],     bz0 = bhh[H + j0],     bn0 = bhh[2 * H + j0];
    float br1 = bhh[j0 + 1], bz1 = bhh[H + j0 + 1], bn1 = bhh[2 * H + j0 + 1];

    for (int i = 0; i < S; i++) {
        int t = dir ? (S - 1 - i) : i;
        const float* hin = (i & 1) ? hbuf1 : hbuf0;
        float* hout = (i & 1) ? hbuf0 : hbuf1;

        float ar0 = br0, az0 = bz0, an0 = bn0;
        float ar1 = br1, az1 = bz1, an1 = bn1;
#pragma unroll 2
        for (int k4 = 0; k4 < H / 4; k4++) {
            float4 h4 = *(const float4*)(hin + (k4 * B + lane) * 4);
            int k = k4 * 4;
            float4 r0 = *(const float4*)(wr + k);
            float4 r1 = *(const float4*)(wr + H + k);
            float4 z0 = *(const float4*)(wz + k);
            float4 z1 = *(const float4*)(wz + H + k);
            float4 n0 = *(const float4*)(wn + k);
            float4 n1 = *(const float4*)(wn + H + k);
            ar0 = fmaf(r0.x, h4.x, ar0); ar0 = fmaf(r0.y, h4.y, ar0); ar0 = fmaf(r0.z, h4.z, ar0); ar0 = fmaf(r0.w, h4.w, ar0);
            ar1 = fmaf(r1.x, h4.x, ar1); ar1 = fmaf(r1.y, h4.y, ar1); ar1 = fmaf(r1.z, h4.z, ar1); ar1 = fmaf(r1.w, h4.w, ar1);
            az0 = fmaf(z0.x, h4.x, az0); az0 = fmaf(z0.y, h4.y, az0); az0 = fmaf(z0.z, h4.z, az0); az0 = fmaf(z0.w, h4.w, az0);
            az1 = fmaf(z1.x, h4.x, az1); az1 = fmaf(z1.y, h4.y, az1); az1 = fmaf(z1.z, h4.z, az1); az1 = fmaf(z1.w, h4.w, az1);
            an0 = fmaf(n0.x, h4.x, an0); an0 = fmaf(n0.y, h4.y, an0); an0 = fmaf(n0.z, h4.z, an0); an0 = fmaf(n0.w, h4.w, an0);
            an1 = fmaf(n1.x, h4.x, an1); an1 = fmaf(n1.y, h4.y, an1); an1 = fmaf(n1.z, h4.z, an1); an1 = fmaf(n1.w, h4.w, an1);
        }

        int base = (lane * S + t) * G3;
        int mask = t < len;
#pragma unroll
        for (int jj = 0; jj < 2; jj++) {
            int j = j0 + jj;
            float ar = jj ? ar1 : ar0, az = jj ? az1 : az0, an = jj ? an1 : an0;
            float r = sigm(gx[base + j] + ar);
            float z = sigm(gx[base + H + j] + az);
            float n = tanhf(gx[base + 2 * H + j] + r * an);
            int hidx = (j >> 2) * (B * 4) + lane * 4 + (j & 3);
            float hprev = hin[hidx];
            float hnew = (1.f - z) * n + z * hprev;
            hout[hidx] = mask ? hnew : hprev;
            g_srchid[(size_t)(lane * S + t) * (2 * H) + dir * H + j] = mask ? hnew : 0.f;
        }
        if (i < S - 1) grid_sync(ENC_BLOCKS);
    }
}

// ---------------- persistent decoder: all T steps, 4 phases each ----------------
__global__ __launch_bounds__(128) void dec_persist(
    const float* __restrict__ dec_Whh, const float* __restrict__ dec_bhh,
    const float* __restrict__ A_W, const float* __restrict__ A_b,
    const float* __restrict__ A_v, const float* __restrict__ dec_Wih,
    const int* __restrict__ src_lengths, const int* __restrict__ tgt_lengths)
{
    __shared__ float s_alpha[S];
    int tid = threadIdx.x;
    int lane = tid & 31;
    int w = tid >> 5;
    int bx = blockIdx.x;

    // ---- phase-1 mapping: 4 j per thread ----
    int j0 = bx * 16 + w * 4;
    bool is_att = (j0 >= G3);
    const float* wp[4];
    float bias1[4];
#pragma unroll
    for (int jj = 0; jj < 4; jj++) {
        int j = j0 + jj;
        if (!is_att) { wp[jj] = dec_Whh + (size_t)j * H; bias1[jj] = dec_bhh[j]; }
        else { int ja = j - G3; wp[jj] = A_W + (size_t)ja * H; bias1[jj] = A_b[ja]; }
    }

    // ---- phase-2 mapping ----
    int b2 = bx & 31, q2 = bx >> 5;
    int len2 = src_lengths[b2];
    float av[16];
#pragma unroll
    for (int m = 0; m < 16; m++) av[m] = A_v[lane + m * 32];

    // ---- phase-3 mapping: 1 j per thread (warp) ----
    int jh = bx * 4 + w;
    const float* w3r = dec_Wih + (size_t)jh * G3 + 512;
    const float* w3z = dec_Wih + (size_t)(512 + jh) * G3 + 512;
    const float* w3n = dec_Wih + (size_t)(1024 + jh) * G3 + 512;
    int mylen = tgt_lengths[lane];

    for (int i = 0; i < T; i++) {
        // ======== phase 1: gh = h@Whh^T + bhh ; Ah = h@A_W^T + A_b ========
        {
            const float* hin = g_hTd[i & 1];
            float acc[4] = {bias1[0], bias1[1], bias1[2], bias1[3]};
#pragma unroll 2
            for (int k4 = 0; k4 < H / 4; k4++) {
                float4 h4 = *(const float4*)(hin + (k4 * B + lane) * 4);
                int k = k4 * 4;
#pragma unroll
                for (int jj = 0; jj < 4; jj++) {
                    float4 wv = *(const float4*)(wp[jj] + k);
                    acc[jj] = fmaf(wv.x, h4.x, acc[jj]);
                    acc[jj] = fmaf(wv.y, h4.y, acc[jj]);
                    acc[jj] = fmaf(wv.z, h4.z, acc[jj]);
                    acc[jj] = fmaf(wv.w, h4.w, acc[jj]);
                }
            }
#pragma unroll
            for (int jj = 0; jj < 4; jj++) {
                int j = j0 + jj;
                if (!is_att) g_ghd[j * B + lane] = acc[jj];
                else g_Ah[lane * H + (j - G3)] = acc[jj];
            }
        }
        grid_sync(DEC_BLOCKS);

        // ======== phase 2a: attention scores ========
        {
            float ah[16];
#pragma unroll
            for (int m = 0; m < 16; m++) ah[m] = g_Ah[b2 * H + lane + m * 32];
#pragma unroll
            for (int si = 0; si < 4; si++) {
                int s = q2 * 16 + w * 4 + si;
                const float* uh = g_Uh + (size_t)(b2 * S + s) * H;
                float p = 0.f;
#pragma unroll
                for (int m = 0; m < 16; m++)
                    p = fmaf(av[m], tanh_fast(uh[lane + m * 32] + ah[m]), p);
#pragma unroll
                for (int off = 16; off; off >>= 1) p += __shfl_xor_sync(0xffffffffu, p, off);
                if (lane == 0) g_escore[b2 * S + s] = (s < len2) ? p : -1e9f;
            }
        }
        grid_sync(DEC_BLOCKS);

        // ======== phase 2b: softmax (replicated per CTA) + context ========
        {
            if (w == 0) {
                float e0 = g_escore[b2 * S + lane];
                float e1 = g_escore[b2 * S + lane + 32];
                float m = fmaxf(e0, e1);
#pragma unroll
                for (int off = 16; off; off >>= 1) m = fmaxf(m, __shfl_xor_sync(0xffffffffu, m, off));
                float x0 = __expf(e0 - m), x1 = __expf(e1 - m);
                float sm = x0 + x1;
#pragma unroll
                for (int off = 16; off; off >>= 1) sm += __shfl_xor_sync(0xffffffffu, sm, off);
                float inv = 1.0f / sm;
                s_alpha[lane] = x0 * inv;
                s_alpha[lane + 32] = x1 * inv;
            }
            __syncthreads();
            int k2 = q2 * 256 + tid * 2;
            const float* sh = g_srchid + (size_t)(b2 * S) * (2 * H) + k2;
            float a0 = 0.f, a1 = 0.f;
#pragma unroll 8
            for (int s = 0; s < S; s++) {
                float2 v = *(const float2*)(sh + (size_t)s * (2 * H));
                float al = s_alpha[s];
                a0 = fmaf(al, v.x, a0);
                a1 = fmaf(al, v.y, a1);
            }
            int cidx = (k2 >> 2) * (B * 4) + b2 * 4 + (k2 & 3);
            g_cT[cidx] = a0;
            g_cT[cidx + 1] = a1;   // k2+1 has same k4, next component
        }
        grid_sync(DEC_BLOCKS);

        // ======== phase 3: gx_c = c@Wih_c^T, gates, h update ========
        {
            float ar = 0.f, az = 0.f, an = 0.f;
#pragma unroll 2
            for (int k4 = 0; k4 < (2 * H) / 4; k4++) {
                float4 c4 = *(const float4*)(g_cT + (k4 * B + lane) * 4);
                int k = k4 * 4;
                float4 r4 = *(const float4*)(w3r + k);
                float4 z4 = *(const float4*)(w3z + k);
                float4 n4 = *(const float4*)(w3n + k);
                ar = fmaf(r4.x, c4.x, ar); ar = fmaf(r4.y, c4.y, ar); ar = fmaf(r4.z, c4.z, ar); ar = fmaf(r4.w, c4.w, ar);
                az = fmaf(z4.x, c4.x, az); az = fmaf(z4.y, c4.y, az); az = fmaf(z4.z, c4.z, az); az = fmaf(z4.w, c4.w, az);
                an = fmaf(n4.x, c4.x, an); an = fmaf(n4.y, c4.y, an); an = fmaf(n4.z, c4.z, an); an = fmaf(n4.w, c4.w, an);
            }
            int base = (lane * T + i) * G3;
            float gxr = g_gxemb[base + jh] + ar;
            float gxz = g_gxemb[base + 512 + jh] + az;
            float gxn = g_gxemb[base + 1024 + jh] + an;
            float ghr = g_ghd[jh * B + lane];
            float ghz = g_ghd[(512 + jh) * B + lane];
            float ghn = g_ghd[(1024 + jh) * B + lane];
            float r = sigm(gxr + ghr);
            float z = sigm(gxz + ghz);
            float n = tanhf(gxn + r * ghn);
            int hidx = (jh >> 2) * (B * 4) + lane * 4 + (jh & 3);
            float hprev = g_hTd[i & 1][hidx];
            float hnew = (1.f - z) * n + z * hprev;
            int mask = i < mylen;
            g_hTd[(i + 1) & 1][hidx] = mask ? hnew : hprev;
            g_decout[(size_t)(lane * T + i) * H + jh] = mask ? hnew : 0.f;
        }
        if (i < T - 1) grid_sync(DEC_BLOCKS);
    }
}

// ---------------- per-row logsumexp + picked logprob ----------------
__global__ __launch_bounds__(256) void row_lse(const int* __restrict__ tgt_seqs)
{
    int row = blockIdx.x;
    int b = row / T, t = row % T;
    const float* lg = g_logits + (size_t)row * V;
    __shared__ float sred[256];
    int tid = threadIdx.x;

    float m = -1e30f;
    for (int v = tid; v < V; v += 256) m = fmaxf(m, lg[v]);
    sred[tid] = m; __syncthreads();
    for (int s2 = 128; s2; s2 >>= 1) {
        if (tid < s2) sred[tid] = fmaxf(sred[tid], sred[tid + s2]);
        __syncthreads();
    }
    m = sred[0]; __syncthreads();

    float ss = 0.f;
    for (int v = tid; v < V; v += 256) ss += expf(lg[v] - m);
    sred[tid] = ss; __syncthreads();
    for (int s2 = 128; s2; s2 >>= 1) {
        if (tid < s2) sred[tid] += sred[tid + s2];
        __syncthreads();
    }
    if (tid == 0) {
        int goal = (t < T - 1) ? tgt_seqs[b * T + t + 1] : 0;
        float lse = m + logf(sred[0]);
        g_rowres[row] = (goal != 0) ? (lg[goal] - lse) : 0.f;
    }
}

// ---------------- final deterministic reduction ----------------
__global__ __launch_bounds__(256) void final_loss(
    const int* __restrict__ tgt_seqs, float* __restrict__ out)
{
    __shared__ float sp[256];
    __shared__ float sc[256];
    int tid = threadIdx.x;
    float ps = 0.f, pc = 0.f;
    for (int r = tid; r < B * T; r += 256) {
        ps += g_rowres[r];
        int b = r / T, t = r % T;
        int goal = (t < T - 1) ? tgt_seqs[b * T + t + 1] : 0;
        pc += (goal != 0) ? 1.f : 0.f;
    }
    sp[tid] = ps; sc[tid] = pc; __syncthreads();
    for (int s2 = 128; s2; s2 >>= 1) {
        if (tid < s2) { sp[tid] += sp[tid + s2]; sc[tid] += sc[tid + s2]; }
        __syncthreads();
    }
    if (tid == 0) out[0] = -sp[0] / sc[0];
}

// ---------------- host ----------------
extern "C" void kernel_launch(void* const* d_in, const int* in_sizes, int n_in,
                              void* d_out, int out_size)
{
    const int* src_seqs    = (const int*)d_in[0];
    const int* src_lengths = (const int*)d_in[1];
    const int* tgt_seqs    = (const int*)d_in[2];
    const int* tgt_lengths = (const int*)d_in[3];
    const float* src_emb   = (const float*)d_in[4];
    const float* enc_Wih_f = (const float*)d_in[5];
    const float* enc_Whh_f = (const float*)d_in[6];
    const float* enc_bih_f = (const float*)d_in[7];
    const float* enc_bhh_f = (const float*)d_in[8];
    const float* enc_Wih_b = (const float*)d_in[9];
    const float* enc_Whh_b = (const float*)d_in[10];
    const float* enc_bih_b = (const float*)d_in[11];
    const float* enc_bhh_b = (const float*)d_in[12];
    const float* tgt_emb   = (const float*)d_in[13];
    const float* dec_Wih   = (const float*)d_in[14];
    const float* dec_Whh   = (const float*)d_in[15];
    const float* dec_bih   = (const float*)d_in[16];
    const float* dec_bhh   = (const float*)d_in[17];
    const float* U_w       = (const float*)d_in[18];
    const float* U_b       = (const float*)d_in[19];
    const float* A_W       = (const float*)d_in[20];
    const float* A_b       = (const float*)d_in[21];
    const float* A_v       = (const float*)d_in[22];
    const float* out_w     = (const float*)d_in[23];
    const float* out_b     = (const float*)d_in[24];

    void *p_esrc, *p_etgt, *p_gxf, *p_gxb, *p_gxemb, *p_srchid, *p_Uh, *p_decout, *p_logits;
    cudaGetSymbolAddress(&p_esrc, g_esrc);
    cudaGetSymbolAddress(&p_etgt, g_etgt);
    cudaGetSymbolAddress(&p_gxf, g_gxf);
    cudaGetSymbolAddress(&p_gxb, g_gxb);
    cudaGetSymbolAddress(&p_gxemb, g_gxemb);
    cudaGetSymbolAddress(&p_srchid, g_srchid);
    cudaGetSymbolAddress(&p_Uh, g_Uh);
    cudaGetSymbolAddress(&p_decout, g_decout);
    cudaGetSymbolAddress(&p_logits, g_logits);

    zero_h_kernel<<<(H * B + 255) / 256, 256>>>();
    embed_kernel<<<B * S + B * T, 128>>>(src_seqs, tgt_seqs, src_emb, tgt_emb);

    // gx precompute GEMMs
    gemm_nt<<<dim3(G3 / GBN, (B * S) / GBM), 256>>>(
        (const float*)p_esrc, E, enc_Wih_f, E, enc_bih_f, (float*)p_gxf, G3, E);
    gemm_nt<<<dim3(G3 / GBN, (B * S) / GBM), 256>>>(
        (const float*)p_esrc, E, enc_Wih_b, E, enc_bih_b, (float*)p_gxb, G3, E);
    gemm_nt<<<dim3(G3 / GBN, (B * T) / GBM), 256>>>(
        (const float*)p_etgt, E, dec_Wih, G3, dec_bih, (float*)p_gxemb, G3, E);

    // persistent encoder (all S steps in one launch)
    enc_persist<<<ENC_BLOCKS, 128>>>(enc_Whh_f, enc_bhh_f, enc_Whh_b, enc_bhh_b, src_lengths);

    // Uh = src_hidden @ U_w^T + U_b
    gemm_nt<<<dim3(H / GBN, (B * S) / GBM), 256>>>(
        (const float*)p_srchid, 2 * H, U_w, 2 * H, U_b, (float*)p_Uh, H, 2 * H);

    // persistent decoder (all T steps in one launch)
    dec_persist<<<DEC_BLOCKS, 128>>>(dec_Whh, dec_bhh, A_W, A_b, A_v, dec_Wih,
                                     src_lengths, tgt_lengths);

    // logits = dec_out @ out_w^T + out_b
    gemm_nt<<<dim3(V / GBN, (B * T) / GBM), 256>>>(
        (const float*)p_decout, H, out_w, H, out_b, (float*)p_logits, V, H);

    row_lse<<<B * T, 256>>>(tgt_seqs);
    final_loss<<<1, 256>>>(tgt_seqs, (float*)d_out);
}

// round 6
// speedup vs baseline: 1.4582x; 1.4582x over previous
#include <cuda_runtime.h>
#include <cuda_bf16.h>
#include <math.h>

#define B 32
#define S 64
#define T 64
#define E 512
#define H 512
#define V 32000
#define G3 1536

#define ENC_BLOCKS 128
#define DEC_BLOCKS 128

__device__ float g_esrc[B * S * E];
__device__ float g_etgt[B * T * E];
__device__ float g_gxf[B * S * G3];          // [t][j][b]
__device__ float g_gxb[B * S * G3];          // [t][j][b]
__device__ float g_gxemb[B * T * G3];        // [i][j][b]
__device__ float g_srchid[B * S * 2 * H];    // [b][s][2H]
__device__ float g_Uh[B * S * H];
__device__ float g_hTf[2][H * B];            // packed float4: (k4*B+b)*4+c
__device__ float g_hTb[2][H * B];
__device__ float g_hTd[2][H * B];
__device__ float g_ghd[G3 * B];
__device__ float g_Ah[B * H];
__device__ float g_cT[2 * H * B];
__device__ float g_decout[B * T * H];
__device__ float g_logits[(size_t)B * T * V];
__device__ float g_rowres[B * T];
__device__ __nv_bfloat16 g_wbf[(size_t)V * H];
__device__ __nv_bfloat16 g_abf[B * T * H];
__device__ unsigned g_cnt_arr[32];
__device__ unsigned g_gen_arr[32];

__device__ __forceinline__ float sigm(float x) { return 1.0f / (1.0f + expf(-x)); }
__device__ __forceinline__ float tanh_fast(float x) {
    float y; asm("tanh.approx.f32 %0, %1;" : "=f"(y) : "f"(x)); return y;
}
__device__ __forceinline__ unsigned ld_acq(unsigned* p) {
    unsigned v; asm volatile("ld.acquire.gpu.u32 %0, [%1];" : "=r"(v) : "l"(p) : "memory"); return v;
}
__device__ __forceinline__ unsigned atom_inc_acqrel(unsigned* p) {
    unsigned o; asm volatile("atom.acq_rel.gpu.add.u32 %0, [%1], 1;" : "=r"(o) : "l"(p) : "memory"); return o;
}
__device__ __forceinline__ void st_rel(unsigned* p, unsigned v) {
    asm volatile("st.release.gpu.u32 [%0], %1;" :: "l"(p), "r"(v) : "memory");
}
// fence-free grid barrier: no CCTL.IVALL, L1 stays warm
__device__ __forceinline__ void grid_sync(unsigned nb) {
    __syncthreads();
    if (threadIdx.x == 0) {
        unsigned gen = ld_acq(&g_gen_arr[0]);
        if (atom_inc_acqrel(&g_cnt_arr[0]) == nb - 1) {
            g_cnt_arr[0] = 0;
            st_rel(&g_gen_arr[0], gen + 1);
        } else {
            while (ld_acq(&g_gen_arr[0]) == gen) { __nanosleep(32); }
        }
    }
    __syncthreads();
}

__global__ void zero_h_kernel() {
    int idx = blockIdx.x * blockDim.x + threadIdx.x;
    if (idx < H * B) { g_hTf[0][idx] = 0.f; g_hTb[0][idx] = 0.f; g_hTd[0][idx] = 0.f; }
    if (idx == 0) { g_cnt_arr[0] = 0; g_gen_arr[0] = 0; }
}

__global__ __launch_bounds__(128) void embed_kernel(
    const int* __restrict__ src_seqs, const int* __restrict__ tgt_seqs,
    const float* __restrict__ src_emb, const float* __restrict__ tgt_emb)
{
    int blk = blockIdx.x, tid = threadIdx.x;
    if (blk < B * S) {
        int tok = src_seqs[blk];
        ((float4*)(g_esrc + (size_t)blk * E))[tid] = ((const float4*)(src_emb + (size_t)tok * E))[tid];
    } else {
        int r = blk - B * S;
        int tok = tgt_seqs[r];
        ((float4*)(g_etgt + (size_t)r * E))[tid] = ((const float4*)(tgt_emb + (size_t)tok * E))[tid];
    }
}

// ---------------- fp32 GEMM: C[M,N]=A[M,K]@W[N,K]^T+bias; TR=1 writes [s][n][b] ----------------
#define GBM 128
#define GBN 64
#define GBK 16
template<int TR>
__global__ __launch_bounds__(256) void gemm_nt(
    const float* __restrict__ A, int lda,
    const float* __restrict__ W, int ldw,
    const float* __restrict__ bias,
    float* __restrict__ C, int ldc, int K, int sdim)
{
    __shared__ float As[GBK][GBM];
    __shared__ float Bs[GBK][GBN];
    int tid = threadIdx.x;
    int m0 = blockIdx.y * GBM, n0 = blockIdx.x * GBN;
    int tx = tid & 15, ty = tid >> 4;
    float acc[8][4];
#pragma unroll
    for (int i = 0; i < 8; i++)
#pragma unroll
        for (int j = 0; j < 4; j++) acc[i][j] = 0.f;
    int ar0 = tid >> 2, ak0 = (tid & 3) * 4;
    for (int k0 = 0; k0 < K; k0 += GBK) {
#pragma unroll
        for (int h = 0; h < 2; h++) {
            int r = ar0 + h * 64;
            float4 v = *(const float4*)(A + (size_t)(m0 + r) * lda + k0 + ak0);
            As[ak0 + 0][r] = v.x; As[ak0 + 1][r] = v.y; As[ak0 + 2][r] = v.z; As[ak0 + 3][r] = v.w;
        }
        {
            float4 v = *(const float4*)(W + (size_t)(n0 + ar0) * ldw + k0 + ak0);
            Bs[ak0 + 0][ar0] = v.x; Bs[ak0 + 1][ar0] = v.y; Bs[ak0 + 2][ar0] = v.z; Bs[ak0 + 3][ar0] = v.w;
        }
        __syncthreads();
#pragma unroll
        for (int kk = 0; kk < GBK; kk++) {
            float a[8], b[4];
#pragma unroll
            for (int i = 0; i < 8; i++) a[i] = As[kk][ty * 8 + i];
#pragma unroll
            for (int j = 0; j < 4; j++) b[j] = Bs[kk][tx * 4 + j];
#pragma unroll
            for (int i = 0; i < 8; i++)
#pragma unroll
                for (int j = 0; j < 4; j++) acc[i][j] = fmaf(a[i], b[j], acc[i][j]);
        }
        __syncthreads();
    }
    float b4[4];
#pragma unroll
    for (int j = 0; j < 4; j++) b4[j] = bias[n0 + tx * 4 + j];
#pragma unroll
    for (int i = 0; i < 8; i++) {
        int m = m0 + ty * 8 + i;
        if (TR) {
            int bb = m / sdim, s = m % sdim;
#pragma unroll
            for (int j = 0; j < 4; j++)
                C[((size_t)s * G3 + n0 + tx * 4 + j) * B + bb] = acc[i][j] + b4[j];
        } else {
            float4 o;
            o.x = acc[i][0] + b4[0]; o.y = acc[i][1] + b4[1];
            o.z = acc[i][2] + b4[2]; o.w = acc[i][3] + b4[3];
            *(float4*)(C + (size_t)m * ldc + n0 + tx * 4) = o;
        }
    }
}

// ---------------- persistent encoder ----------------
__global__ __launch_bounds__(128) void enc_persist(
    const float* __restrict__ Whh_f, const float* __restrict__ bhh_f,
    const float* __restrict__ Whh_b, const float* __restrict__ bhh_b,
    const int* __restrict__ src_lengths)
{
    int lane = threadIdx.x & 31;           // = b
    int w = threadIdx.x >> 5;
    int bx = blockIdx.x;
    int dir = bx >> 6;
    int j0 = (bx & 63) * 8 + w * 2;
    const float* gx = dir ? g_gxb : g_gxf;
    const float* Whh = dir ? Whh_b : Whh_f;
    const float* bhh = dir ? bhh_b : bhh_f;
    float* hbuf0 = dir ? g_hTb[0] : g_hTf[0];
    float* hbuf1 = dir ? g_hTb[1] : g_hTf[1];
    int len = src_lengths[lane];

    const float* wr = Whh + (size_t)j0 * H;
    const float* wz = Whh + (size_t)(H + j0) * H;
    const float* wn = Whh + (size_t)(2 * H + j0) * H;
    float br0 = bhh[j0],     bz0 = bhh[H + j0],     bn0 = bhh[2 * H + j0];
    float br1 = bhh[j0 + 1], bz1 = bhh[H + j0 + 1], bn1 = bhh[2 * H + j0 + 1];

    for (int i = 0; i < S; i++) {
        int t = dir ? (S - 1 - i) : i;
        const float* hin = (i & 1) ? hbuf1 : hbuf0;
        float* hout = (i & 1) ? hbuf0 : hbuf1;
        float ar0 = br0, az0 = bz0, an0 = bn0, ar1 = br1, az1 = bz1, an1 = bn1;
#pragma unroll 4
        for (int k4 = 0; k4 < H / 4; k4++) {
            float4 h4 = __ldcg((const float4*)(hin + (k4 * B + lane) * 4));
            int k = k4 * 4;
            float4 r0 = *(const float4*)(wr + k);
            float4 r1 = *(const float4*)(wr + H + k);
            float4 z0 = *(const float4*)(wz + k);
            float4 z1 = *(const float4*)(wz + H + k);
            float4 n0 = *(const float4*)(wn + k);
            float4 n1 = *(const float4*)(wn + H + k);
            ar0 = fmaf(r0.x, h4.x, ar0); ar0 = fmaf(r0.y, h4.y, ar0); ar0 = fmaf(r0.z, h4.z, ar0); ar0 = fmaf(r0.w, h4.w, ar0);
            ar1 = fmaf(r1.x, h4.x, ar1); ar1 = fmaf(r1.y, h4.y, ar1); ar1 = fmaf(r1.z, h4.z, ar1); ar1 = fmaf(r1.w, h4.w, ar1);
            az0 = fmaf(z0.x, h4.x, az0); az0 = fmaf(z0.y, h4.y, az0); az0 = fmaf(z0.z, h4.z, az0); az0 = fmaf(z0.w, h4.w, az0);
            az1 = fmaf(z1.x, h4.x, az1); az1 = fmaf(z1.y, h4.y, az1); az1 = fmaf(z1.z, h4.z, az1); az1 = fmaf(z1.w, h4.w, az1);
            an0 = fmaf(n0.x, h4.x, an0); an0 = fmaf(n0.y, h4.y, an0); an0 = fmaf(n0.z, h4.z, an0); an0 = fmaf(n0.w, h4.w, an0);
            an1 = fmaf(n1.x, h4.x, an1); an1 = fmaf(n1.y, h4.y, an1); an1 = fmaf(n1.z, h4.z, an1); an1 = fmaf(n1.w, h4.w, an1);
        }
        int mask = t < len;
        const float* gxt = gx + (size_t)t * G3 * B;
#pragma unroll
        for (int jj = 0; jj < 2; jj++) {
            int j = j0 + jj;
            float ar = jj ? ar1 : ar0, az = jj ? az1 : az0, an = jj ? an1 : an0;
            float r = sigm(gxt[(size_t)j * B + lane] + ar);
            float z = sigm(gxt[(size_t)(H + j) * B + lane] + az);
            float n = tanhf(gxt[(size_t)(2 * H + j) * B + lane] + r * an);
            int hidx = (j >> 2) * (B * 4) + lane * 4 + (j & 3);
            float hprev = __ldcg(hin + hidx);
            float hnew = (1.f - z) * n + z * hprev;
            hout[hidx] = mask ? hnew : hprev;
            g_srchid[(size_t)(lane * S + t) * (2 * H) + dir * H + j] = mask ? hnew : 0.f;
        }
        if (i < S - 1) grid_sync(ENC_BLOCKS);
    }
}

// ---------------- persistent decoder: 3 phases/step ----------------
__global__ __launch_bounds__(128) void dec_persist(
    const float* __restrict__ dec_Whh, const float* __restrict__ dec_bhh,
    const float* __restrict__ A_W, const float* __restrict__ A_b,
    const float* __restrict__ A_v, const float* __restrict__ dec_Wih,
    const int* __restrict__ src_lengths, const int* __restrict__ tgt_lengths)
{
    __shared__ float se[S];
    int tid = threadIdx.x, lane = tid & 31, w = tid >> 5, bx = blockIdx.x;

    // phase-1 mapping
    int j0 = bx * 16 + w * 4;
    bool is_att = (j0 >= G3);
    const float* wp[4];
    float bias1[4];
#pragma unroll
    for (int jj = 0; jj < 4; jj++) {
        int j = j0 + jj;
        if (!is_att) { wp[jj] = dec_Whh + (size_t)j * H; bias1[jj] = dec_bhh[j]; }
        else { int ja = j - G3; wp[jj] = A_W + (size_t)ja * H; bias1[jj] = A_b[ja]; }
    }
    // phase-2 mapping
    int b2 = bx & 31, q2 = bx >> 5;
    int len2 = src_lengths[b2];
    float av[16];
#pragma unroll
    for (int m = 0; m < 16; m++) av[m] = A_v[lane + m * 32];
    // phase-3 mapping
    int jh = bx * 4 + w;
    const float* w3r = dec_Wih + (size_t)jh * G3 + 512;
    const float* w3z = dec_Wih + (size_t)(512 + jh) * G3 + 512;
    const float* w3n = dec_Wih + (size_t)(1024 + jh) * G3 + 512;
    int mylen = tgt_lengths[lane];

    for (int i = 0; i < T; i++) {
        // ---- phase 1: gh, Ah ----
        {
            const float* hin = g_hTd[i & 1];
            float acc[4] = {bias1[0], bias1[1], bias1[2], bias1[3]};
#pragma unroll 4
            for (int k4 = 0; k4 < H / 4; k4++) {
                float4 h4 = __ldcg((const float4*)(hin + (k4 * B + lane) * 4));
                int k = k4 * 4;
#pragma unroll
                for (int jj = 0; jj < 4; jj++) {
                    float4 wv = *(const float4*)(wp[jj] + k);
                    acc[jj] = fmaf(wv.x, h4.x, acc[jj]);
                    acc[jj] = fmaf(wv.y, h4.y, acc[jj]);
                    acc[jj] = fmaf(wv.z, h4.z, acc[jj]);
                    acc[jj] = fmaf(wv.w, h4.w, acc[jj]);
                }
            }
#pragma unroll
            for (int jj = 0; jj < 4; jj++) {
                int j = j0 + jj;
                if (!is_att) g_ghd[j * B + lane] = acc[jj];
                else g_Ah[lane * H + (j - G3)] = acc[jj];
            }
        }
        grid_sync(DEC_BLOCKS);

        // ---- phase 2: scores (all s for b2) + softmax + context (k-quarter) ----
        {
            float ah[16];
#pragma unroll
            for (int m = 0; m < 16; m++) ah[m] = __ldcg(g_Ah + b2 * H + lane + m * 32);
#pragma unroll
            for (int si = 0; si < 16; si++) {
                int s = w * 16 + si;
                const float* uh = g_Uh + (size_t)(b2 * S + s) * H;
                float p = 0.f;
#pragma unroll
                for (int m = 0; m < 16; m++)
                    p = fmaf(av[m], tanh_fast(uh[lane + m * 32] + ah[m]), p);
#pragma unroll
                for (int off = 16; off; off >>= 1) p += __shfl_xor_sync(0xffffffffu, p, off);
                if (lane == 0) se[s] = (s < len2) ? p : -1e9f;
            }
            __syncthreads();
            if (w == 0) {
                float e0 = se[lane], e1 = se[lane + 32];
                float m = fmaxf(e0, e1);
#pragma unroll
                for (int off = 16; off; off >>= 1) m = fmaxf(m, __shfl_xor_sync(0xffffffffu, m, off));
                float x0 = __expf(e0 - m), x1 = __expf(e1 - m);
                float sm = x0 + x1;
#pragma unroll
                for (int off = 16; off; off >>= 1) sm += __shfl_xor_sync(0xffffffffu, sm, off);
                float inv = 1.0f / sm;
                se[lane] = x0 * inv; se[lane + 32] = x1 * inv;
            }
            __syncthreads();
            int k2 = q2 * 256 + tid * 2;
            const float* sh = g_srchid + (size_t)(b2 * S) * (2 * H) + k2;
            float a0 = 0.f, a1 = 0.f;
#pragma unroll 8
            for (int s = 0; s < S; s++) {
                float2 v = *(const float2*)(sh + (size_t)s * (2 * H));
                float al = se[s];
                a0 = fmaf(al, v.x, a0); a1 = fmaf(al, v.y, a1);
            }
            int cidx = (k2 >> 2) * (B * 4) + b2 * 4 + (k2 & 3);
            g_cT[cidx] = a0; g_cT[cidx + 1] = a1;
        }
        grid_sync(DEC_BLOCKS);

        // ---- phase 3: gates + h update ----
        {
            float ar = 0.f, az = 0.f, an = 0.f;
#pragma unroll 4
            for (int k4 = 0; k4 < (2 * H) / 4; k4++) {
                float4 c4 = __ldcg((const float4*)(g_cT + (k4 * B + lane) * 4));
                int k = k4 * 4;
                float4 r4 = *(const float4*)(w3r + k);
                float4 z4 = *(const float4*)(w3z + k);
                float4 n4 = *(const float4*)(w3n + k);
                ar = fmaf(r4.x, c4.x, ar); ar = fmaf(r4.y, c4.y, ar); ar = fmaf(r4.z, c4.z, ar); ar = fmaf(r4.w, c4.w, ar);
                az = fmaf(z4.x, c4.x, az); az = fmaf(z4.y, c4.y, az); az = fmaf(z4.z, c4.z, az); az = fmaf(z4.w, c4.w, az);
                an = fmaf(n4.x, c4.x, an); an = fmaf(n4.y, c4.y, an); an = fmaf(n4.z, c4.z, an); an = fmaf(n4.w, c4.w, an);
            }
            const float* gxt = g_gxemb + (size_t)i * G3 * B;
            float gxr = gxt[(size_t)jh * B + lane] + ar;
            float gxz = gxt[(size_t)(512 + jh) * B + lane] + az;
            float gxn = gxt[(size_t)(1024 + jh) * B + lane] + an;
            float ghr = __ldcg(g_ghd + jh * B + lane);
            float ghz = __ldcg(g_ghd + (512 + jh) * B + lane);
            float ghn = __ldcg(g_ghd + (1024 + jh) * B + lane);
            float r = sigm(gxr + ghr);
            float z = sigm(gxz + ghz);
            float n = tanhf(gxn + r * ghn);
            int hidx = (jh >> 2) * (B * 4) + lane * 4 + (jh & 3);
            float hprev = __ldcg(g_hTd[i & 1] + hidx);
            float hnew = (1.f - z) * n + z * hprev;
            int mask = i < mylen;
            g_hTd[(i + 1) & 1][hidx] = mask ? hnew : hprev;
            g_decout[(size_t)(lane * T + i) * H + jh] = mask ? hnew : 0.f;
        }
        if (i < T - 1) grid_sync(DEC_BLOCKS);
    }
}

// ---------------- fp32 -> bf16 ----------------
__global__ __launch_bounds__(256) void cvt_bf16(const float* __restrict__ src,
                                                __nv_bfloat16* __restrict__ dst, int n8)
{
    int i = blockIdx.x * 256 + threadIdx.x;
    if (i < n8) {
        float4 a = ((const float4*)src)[i * 2], b = ((const float4*)src)[i * 2 + 1];
        __nv_bfloat162 o[4];
        o[0] = __nv_bfloat162(__float2bfloat16(a.x), __float2bfloat16(a.y));
        o[1] = __nv_bfloat162(__float2bfloat16(a.z), __float2bfloat16(a.w));
        o[2] = __nv_bfloat162(__float2bfloat16(b.x), __float2bfloat16(b.y));
        o[3] = __nv_bfloat162(__float2bfloat16(b.z), __float2bfloat16(b.w));
        ((uint4*)dst)[i] = *(uint4*)o;
    }
}

// ---------------- bf16 tensor-core logits GEMM ----------------
#define LBM 128
#define LBN 128
#define LBK 32
#define LPAD 8
__device__ __forceinline__ void mma16816(float* d, const unsigned* a, const unsigned* b) {
    asm volatile("mma.sync.aligned.m16n8k16.row.col.f32.bf16.bf16.f32 "
        "{%0,%1,%2,%3},{%4,%5,%6,%7},{%8,%9},{%0,%1,%2,%3};"
        : "+f"(d[0]), "+f"(d[1]), "+f"(d[2]), "+f"(d[3])
        : "r"(a[0]), "r"(a[1]), "r"(a[2]), "r"(a[3]), "r"(b[0]), "r"(b[1]));
}
__global__ __launch_bounds__(256) void gemm_logits(const float* __restrict__ out_b)
{
    __shared__ __nv_bfloat16 As[LBM][LBK + LPAD];
    __shared__ __nv_bfloat16 Ws[LBN][LBK + LPAD];
    int tid = threadIdx.x;
    int m0 = blockIdx.y * LBM, n0 = blockIdx.x * LBN;
    int wid = tid >> 5, lane = tid & 31;
    int wm = (wid & 1) * 64, wn = (wid >> 1) * 32;
    float acc[4][4][4];
#pragma unroll
    for (int a = 0; a < 4; a++)
#pragma unroll
        for (int b = 0; b < 4; b++)
#pragma unroll
            for (int c = 0; c < 4; c++) acc[a][b][c] = 0.f;

    int lr = tid >> 1, lc = (tid & 1) * 16;
    for (int k0 = 0; k0 < H; k0 += LBK) {
        uint4 va  = *(const uint4*)(g_abf + (size_t)(m0 + lr) * H + k0 + lc);
        uint4 va2 = *(const uint4*)(g_abf + (size_t)(m0 + lr) * H + k0 + lc + 8);
        uint4 vw  = *(const uint4*)(g_wbf + (size_t)(n0 + lr) * H + k0 + lc);
        uint4 vw2 = *(const uint4*)(g_wbf + (size_t)(n0 + lr) * H + k0 + lc + 8);
        __syncthreads();
        *(uint4*)&As[lr][lc] = va;  *(uint4*)&As[lr][lc + 8] = va2;
        *(uint4*)&Ws[lr][lc] = vw;  *(uint4*)&Ws[lr][lc + 8] = vw2;
        __syncthreads();
#pragma unroll
        for (int kk = 0; kk < LBK; kk += 16) {
            unsigned af[4][4], bfr[4][2];
            int arow = lane >> 2, acol = kk + (lane & 3) * 2;
#pragma unroll
            for (int mf = 0; mf < 4; mf++) {
                af[mf][0] = *(const unsigned*)&As[wm + mf * 16 + arow][acol];
                af[mf][1] = *(const unsigned*)&As[wm + mf * 16 + arow + 8][acol];
                af[mf][2] = *(const unsigned*)&As[wm + mf * 16 + arow][acol + 8];
                af[mf][3] = *(const unsigned*)&As[wm + mf * 16 + arow + 8][acol + 8];
            }
#pragma unroll
            for (int nf = 0; nf < 4; nf++) {
                int brow = wn + nf * 8 + (lane >> 2);
                bfr[nf][0] = *(const unsigned*)&Ws[brow][acol];
                bfr[nf][1] = *(const unsigned*)&Ws[brow][acol + 8];
            }
#pragma unroll
            for (int mf = 0; mf < 4; mf++)
#pragma unroll
                for (int nf = 0; nf < 4; nf++) mma16816(acc[mf][nf], af[mf], bfr[nf]);
        }
    }
#pragma unroll
    for (int mf = 0; mf < 4; mf++)
#pragma unroll
        for (int nf = 0; nf < 4; nf++) {
            int m = m0 + wm + mf * 16 + (lane >> 2);
            int n = n0 + wn + nf * 8 + (lane & 3) * 2;
            float b0 = out_b[n], b1 = out_b[n + 1];
            float* p = g_logits + (size_t)m * V + n;
            p[0] = acc[mf][nf][0] + b0; p[1] = acc[mf][nf][1] + b1;
            float* p2 = p + (size_t)8 * V;
            p2[0] = acc[mf][nf][2] + b0; p2[1] = acc[mf][nf][3] + b1;
        }
}

// ---------------- online logsumexp per row ----------------
__global__ __launch_bounds__(256) void row_lse(const int* __restrict__ tgt_seqs)
{
    int row = blockIdx.x, b = row / T, t = row % T;
    const float* lg = g_logits + (size_t)row * V;
    int tid = threadIdx.x;
    float m = -1e30f, s = 0.f;
    for (int v = tid; v < V; v += 256) {
        float x = lg[v];
        if (x > m) { s = s * __expf(m - x) + 1.f; m = x; }
        else s += __expf(x - m);
    }
    __shared__ float sm_[256], ss_[256];
    sm_[tid] = m; ss_[tid] = s; __syncthreads();
    for (int q = 128; q; q >>= 1) {
        if (tid < q) {
            float m1 = sm_[tid], s1 = ss_[tid], m2 = sm_[tid + q], s2 = ss_[tid + q];
            float mm = fmaxf(m1, m2);
            sm_[tid] = mm; ss_[tid] = s1 * __expf(m1 - mm) + s2 * __expf(m2 - mm);
        }
        __syncthreads();
    }
    if (tid == 0) {
        int goal = (t < T - 1) ? tgt_seqs[b * T + t + 1] : 0;
        float lse = sm_[0] + logf(ss_[0]);
        g_rowres[row] = (goal != 0) ? (lg[goal] - lse) : 0.f;
    }
}

__global__ __launch_bounds__(256) void final_loss(
    const int* __restrict__ tgt_seqs, float* __restrict__ out)
{
    __shared__ float sp[256], sc[256];
    int tid = threadIdx.x;
    float ps = 0.f, pc = 0.f;
    for (int r = tid; r < B * T; r += 256) {
        ps += g_rowres[r];
        int b = r / T, t = r % T;
        int goal = (t < T - 1) ? tgt_seqs[b * T + t + 1] : 0;
        pc += (goal != 0) ? 1.f : 0.f;
    }
    sp[tid] = ps; sc[tid] = pc; __syncthreads();
    for (int q = 128; q; q >>= 1) {
        if (tid < q) { sp[tid] += sp[tid + q]; sc[tid] += sc[tid + q]; }
        __syncthreads();
    }
    if (tid == 0) out[0] = -sp[0] / sc[0];
}

extern "C" void kernel_launch(void* const* d_in, const int* in_sizes, int n_in,
                              void* d_out, int out_size)
{
    const int* src_seqs    = (const int*)d_in[0];
    const int* src_lengths = (const int*)d_in[1];
    const int* tgt_seqs    = (const int*)d_in[2];
    const int* tgt_lengths = (const int*)d_in[3];
    const float* src_emb   = (const float*)d_in[4];
    const float* enc_Wih_f = (const float*)d_in[5];
    const float* enc_Whh_f = (const float*)d_in[6];
    const float* enc_bih_f = (const float*)d_in[7];
    const float* enc_bhh_f = (const float*)d_in[8];
    const float* enc_Wih_b = (const float*)d_in[9];
    const float* enc_Whh_b = (const float*)d_in[10];
    const float* enc_bih_b = (const float*)d_in[11];
    const float* enc_bhh_b = (const float*)d_in[12];
    const float* tgt_emb   = (const float*)d_in[13];
    const float* dec_Wih   = (const float*)d_in[14];
    const float* dec_Whh   = (const float*)d_in[15];
    const float* dec_bih   = (const float*)d_in[16];
    const float* dec_bhh   = (const float*)d_in[17];
    const float* U_w       = (const float*)d_in[18];
    const float* U_b       = (const float*)d_in[19];
    const float* A_W       = (const float*)d_in[20];
    const float* A_b       = (const float*)d_in[21];
    const float* A_v       = (const float*)d_in[22];
    const float* out_w     = (const float*)d_in[23];
    const float* out_b     = (const float*)d_in[24];

    void *p_esrc, *p_etgt, *p_gxf, *p_gxb, *p_gxemb, *p_srchid, *p_Uh, *p_decout, *p_wbf, *p_abf;
    cudaGetSymbolAddress(&p_esrc, g_esrc);
    cudaGetSymbolAddress(&p_etgt, g_etgt);
    cudaGetSymbolAddress(&p_gxf, g_gxf);
    cudaGetSymbolAddress(&p_gxb, g_gxb);
    cudaGetSymbolAddress(&p_gxemb, g_gxemb);
    cudaGetSymbolAddress(&p_srchid, g_srchid);
    cudaGetSymbolAddress(&p_Uh, g_Uh);
    cudaGetSymbolAddress(&p_decout, g_decout);
    cudaGetSymbolAddress(&p_wbf, g_wbf);
    cudaGetSymbolAddress(&p_abf, g_abf);

    zero_h_kernel<<<(H * B + 255) / 256, 256>>>();
    embed_kernel<<<B * S + B * T, 128>>>(src_seqs, tgt_seqs, src_emb, tgt_emb);

    gemm_nt<1><<<dim3(G3 / GBN, (B * S) / GBM), 256>>>(
        (const float*)p_esrc, E, enc_Wih_f, E, enc_bih_f, (float*)p_gxf, G3, E, S);
    gemm_nt<1><<<dim3(G3 / GBN, (B * S) / GBM), 256>>>(
        (const float*)p_esrc, E, enc_Wih_b, E, enc_bih_b, (float*)p_gxb, G3, E, S);
    gemm_nt<1><<<dim3(G3 / GBN, (B * T) / GBM), 256>>>(
        (const float*)p_etgt, E, dec_Wih, G3, dec_bih, (float*)p_gxemb, G3, E, T);

    enc_persist<<<ENC_BLOCKS, 128>>>(enc_Whh_f, enc_bhh_f, enc_Whh_b, enc_bhh_b, src_lengths);

    gemm_nt<0><<<dim3(H / GBN, (B * S) / GBM), 256>>>(
        (const float*)p_srchid, 2 * H, U_w, 2 * H, U_b, (float*)p_Uh, H, 2 * H, S);

    dec_persist<<<DEC_BLOCKS, 128>>>(dec_Whh, dec_bhh, A_W, A_b, A_v, dec_Wih,
                                     src_lengths, tgt_lengths);

    cvt_bf16<<<(B * T * H / 8 + 255) / 256, 256>>>((const float*)p_decout,
                                                   (__nv_bfloat16*)p_abf, B * T * H / 8);
    cvt_bf16<<<((int)((size_t)V * H / 8) + 255) / 256, 256>>>(out_w,
                                                   (__nv_bfloat16*)p_wbf, (int)((size_t)V * H / 8));

    gemm_logits<<<dim3(V / LBN, (B * T) / LBM), 256>>>(out_b);

    row_lse<<<B * T, 256>>>(tgt_seqs);
    final_loss<<<1, 256>>>(tgt_seqs, (float*)d_out);
}

// round 9
// speedup vs baseline: 3.7682x; 2.5841x over previous
#include <cuda_runtime.h>
#include <cuda_bf16.h>
#include <math.h>

#define B 32
#define S 64
#define T 64
#define E 512
#define H 512
#define V 32000
#define G3 1536

#define ENC_BLOCKS 128
#define DEC_BLOCKS 128

__device__ float g_esrc[B * S * E];
__device__ float g_etgt[B * T * E];
__device__ float g_gxf[B * S * G3];          // [t][j][b]
__device__ float g_gxb[B * S * G3];          // [t][j][b]
__device__ float g_gxemb[B * T * G3];        // [i][j][b]
__device__ float g_srchid[B * S * 2 * H];    // [b][s][2H]
__device__ float g_Uh[B * S * H];
__device__ float g_hTf[2][H * B];            // float4 layout: f4 index k4*B+b
__device__ float g_hTb[2][H * B];
__device__ float g_hTd[2][H * B];
__device__ float g_ghd[G3 * B];
__device__ float g_Ah[B * H];
__device__ float g_cT[2 * H * B];
__device__ float g_decout[B * T * H];
__device__ float g_logits[(size_t)B * T * V];
__device__ float g_rowres[B * T];
__device__ __nv_bfloat16 g_wbf[(size_t)V * H];
__device__ __nv_bfloat16 g_abf[B * T * H];
__device__ unsigned g_cnt_enc[32];
__device__ unsigned g_cnt_dec[32];

__device__ __forceinline__ float sigm(float x) { return 1.0f / (1.0f + expf(-x)); }
__device__ __forceinline__ float tanh_fast(float x) {
    float y; asm("tanh.approx.f32 %0, %1;" : "=f"(y) : "f"(x)); return y;
}

// monotonic grid barrier: relaxed poll (no IVALL in loop), one acq_rel fence each side
__device__ __forceinline__ void bar_sync(unsigned* cnt, unsigned target) {
    __syncthreads();
    if (threadIdx.x == 0) {
        asm volatile("fence.acq_rel.gpu;" ::: "memory");
        asm volatile("red.relaxed.gpu.add.u32 [%0], 1;" :: "l"(cnt) : "memory");
        unsigned v;
        do {
            asm volatile("ld.relaxed.gpu.u32 %0, [%1];" : "=r"(v) : "l"(cnt) : "memory");
        } while (v < target);
        asm volatile("fence.acq_rel.gpu;" ::: "memory");
    }
    __syncthreads();
}

__global__ void zero_h_kernel() {
    int idx = blockIdx.x * blockDim.x + threadIdx.x;
    if (idx < H * B) { g_hTf[0][idx] = 0.f; g_hTb[0][idx] = 0.f; g_hTd[0][idx] = 0.f; }
    if (idx == 0) { g_cnt_enc[0] = 0; g_cnt_dec[0] = 0; }
}

__global__ __launch_bounds__(128) void embed_kernel(
    const int* __restrict__ src_seqs, const int* __restrict__ tgt_seqs,
    const float* __restrict__ src_emb, const float* __restrict__ tgt_emb)
{
    int blk = blockIdx.x, tid = threadIdx.x;
    if (blk < B * S) {
        int tok = src_seqs[blk];
        ((float4*)(g_esrc + (size_t)blk * E))[tid] = ((const float4*)(src_emb + (size_t)tok * E))[tid];
    } else {
        int r = blk - B * S;
        int tok = tgt_seqs[r];
        ((float4*)(g_etgt + (size_t)r * E))[tid] = ((const float4*)(tgt_emb + (size_t)tok * E))[tid];
    }
}

// ---------------- fp32 GEMM: C[M,N]=A[M,K]@W[N,K]^T+bias; TR=1 writes [s][n][b] ----------------
#define GBM 128
#define GBN 64
#define GBK 16
template<int TR>
__global__ __launch_bounds__(256) void gemm_nt(
    const float* __restrict__ A, int lda,
    const float* __restrict__ W, int ldw,
    const float* __restrict__ bias,
    float* __restrict__ C, int ldc, int K, int sdim)
{
    __shared__ float As[GBK][GBM];
    __shared__ float Bs[GBK][GBN];
    int tid = threadIdx.x;
    int m0 = blockIdx.y * GBM, n0 = blockIdx.x * GBN;
    int tx = tid & 15, ty = tid >> 4;
    float acc[8][4];
#pragma unroll
    for (int i = 0; i < 8; i++)
#pragma unroll
        for (int j = 0; j < 4; j++) acc[i][j] = 0.f;
    int ar0 = tid >> 2, ak0 = (tid & 3) * 4;
    for (int k0 = 0; k0 < K; k0 += GBK) {
#pragma unroll
        for (int h = 0; h < 2; h++) {
            int r = ar0 + h * 64;
            float4 v = *(const float4*)(A + (size_t)(m0 + r) * lda + k0 + ak0);
            As[ak0 + 0][r] = v.x; As[ak0 + 1][r] = v.y; As[ak0 + 2][r] = v.z; As[ak0 + 3][r] = v.w;
        }
        {
            float4 v = *(const float4*)(W + (size_t)(n0 + ar0) * ldw + k0 + ak0);
            Bs[ak0 + 0][ar0] = v.x; Bs[ak0 + 1][ar0] = v.y; Bs[ak0 + 2][ar0] = v.z; Bs[ak0 + 3][ar0] = v.w;
        }
        __syncthreads();
#pragma unroll
        for (int kk = 0; kk < GBK; kk++) {
            float a[8], b[4];
#pragma unroll
            for (int i = 0; i < 8; i++) a[i] = As[kk][ty * 8 + i];
#pragma unroll
            for (int j = 0; j < 4; j++) b[j] = Bs[kk][tx * 4 + j];
#pragma unroll
            for (int i = 0; i < 8; i++)
#pragma unroll
                for (int j = 0; j < 4; j++) acc[i][j] = fmaf(a[i], b[j], acc[i][j]);
        }
        __syncthreads();
    }
    float b4[4];
#pragma unroll
    for (int j = 0; j < 4; j++) b4[j] = bias[n0 + tx * 4 + j];
#pragma unroll
    for (int i = 0; i < 8; i++) {
        int m = m0 + ty * 8 + i;
        if (TR) {
            int bb = m / sdim, s = m % sdim;
#pragma unroll
            for (int j = 0; j < 4; j++)
                C[((size_t)s * G3 + n0 + tx * 4 + j) * B + bb] = acc[i][j] + b4[j];
        } else {
            float4 o;
            o.x = acc[i][0] + b4[0]; o.y = acc[i][1] + b4[1];
            o.z = acc[i][2] + b4[2]; o.w = acc[i][3] + b4[3];
            *(float4*)(C + (size_t)m * ldc + n0 + tx * 4) = o;
        }
    }
}

// ---------------- persistent encoder: weights + h staged in SMEM ----------------
extern __shared__ float4 sdyn[];
__global__ __launch_bounds__(128) void enc_persist(
    const float* __restrict__ Whh_f, const float* __restrict__ bhh_f,
    const float* __restrict__ Whh_b, const float* __restrict__ bhh_b,
    const int* __restrict__ src_lengths)
{
    float4* sW = sdyn;          // 3072 f4 = 48KB: [gate][jj 0..7][k4 0..127]
    float4* sH = sdyn + 3072;   // 4096 f4 = 64KB: f4 idx k4*B + b
    int tid = threadIdx.x, lane = tid & 31, w = tid >> 5, bx = blockIdx.x;
    int dir = bx >> 6, j0c = (bx & 63) * 8;
    const float* Whh = dir ? Whh_b : Whh_f;
    const float* bhh = dir ? bhh_b : bhh_f;
    const float* gx = dir ? g_gxb : g_gxf;
    float* hbuf0 = dir ? g_hTb[0] : g_hTf[0];
    float* hbuf1 = dir ? g_hTb[1] : g_hTf[1];
    int len = src_lengths[lane];

    for (int idx = tid; idx < 3072; idx += 128) {
        int g = idx >> 10, rem = idx & 1023, jj = rem >> 7, k4 = rem & 127;
        sW[idx] = ((const float4*)(Whh + (size_t)(g * H + j0c + jj) * H))[k4];
    }
    int jj0 = w * 2;
    int j0 = j0c + jj0;
    float br0 = bhh[j0],     bz0 = bhh[H + j0],     bn0 = bhh[2 * H + j0];
    float br1 = bhh[j0 + 1], bz1 = bhh[H + j0 + 1], bn1 = bhh[2 * H + j0 + 1];
    const float4* base = sW + jj0 * 128;
    unsigned bt = 0;

    for (int i = 0; i < S; i++) {
        int t = dir ? (S - 1 - i) : i;
        const float* hin = (i & 1) ? hbuf1 : hbuf0;
        float* hout = (i & 1) ? hbuf0 : hbuf1;
        __syncthreads();
        for (int idx = tid; idx < 4096; idx += 128)
            sH[idx] = ((const float4*)hin)[idx];
        __syncthreads();

        float ar0 = br0, az0 = bz0, an0 = bn0, ar1 = br1, az1 = bz1, an1 = bn1;
#pragma unroll 4
        for (int k4 = 0; k4 < 128; k4++) {
            float4 h4 = sH[k4 * B + lane];
            float4 r0 = base[k4],        r1 = base[k4 + 128];
            float4 z0 = base[k4 + 1024], z1 = base[k4 + 1152];
            float4 n0 = base[k4 + 2048], n1 = base[k4 + 2176];
            ar0 = fmaf(r0.x, h4.x, ar0); ar0 = fmaf(r0.y, h4.y, ar0); ar0 = fmaf(r0.z, h4.z, ar0); ar0 = fmaf(r0.w, h4.w, ar0);
            ar1 = fmaf(r1.x, h4.x, ar1); ar1 = fmaf(r1.y, h4.y, ar1); ar1 = fmaf(r1.z, h4.z, ar1); ar1 = fmaf(r1.w, h4.w, ar1);
            az0 = fmaf(z0.x, h4.x, az0); az0 = fmaf(z0.y, h4.y, az0); az0 = fmaf(z0.z, h4.z, az0); az0 = fmaf(z0.w, h4.w, az0);
            az1 = fmaf(z1.x, h4.x, az1); az1 = fmaf(z1.y, h4.y, az1); az1 = fmaf(z1.z, h4.z, az1); az1 = fmaf(z1.w, h4.w, az1);
            an0 = fmaf(n0.x, h4.x, an0); an0 = fmaf(n0.y, h4.y, an0); an0 = fmaf(n0.z, h4.z, an0); an0 = fmaf(n0.w, h4.w, an0);
            an1 = fmaf(n1.x, h4.x, an1); an1 = fmaf(n1.y, h4.y, an1); an1 = fmaf(n1.z, h4.z, an1); an1 = fmaf(n1.w, h4.w, an1);
        }
        int mask = t < len;
        const float* gxt = gx + (size_t)t * G3 * B;
#pragma unroll
        for (int jj = 0; jj < 2; jj++) {
            int j = j0 + jj;
            float ar = jj ? ar1 : ar0, az = jj ? az1 : az0, an = jj ? an1 : an0;
            float r = sigm(gxt[(size_t)j * B + lane] + ar);
            float z = sigm(gxt[(size_t)(H + j) * B + lane] + az);
            float n = tanhf(gxt[(size_t)(2 * H + j) * B + lane] + r * an);
            int hidx = (j >> 2) * (B * 4) + lane * 4 + (j & 3);
            float hprev = ((const float*)sH)[hidx];
            float hnew = (1.f - z) * n + z * hprev;
            hout[hidx] = mask ? hnew : hprev;
            g_srchid[(size_t)(lane * S + t) * (2 * H) + dir * H + j] = mask ? hnew : 0.f;
        }
        if (i < S - 1) bar_sync(&g_cnt_enc[0], (++bt) * ENC_BLOCKS);
    }
}

// ---------------- persistent decoder: weights + h/c staged in SMEM ----------------
__global__ __launch_bounds__(128) void dec_persist(
    const float* __restrict__ dec_Whh, const float* __restrict__ dec_bhh,
    const float* __restrict__ A_W, const float* __restrict__ A_b,
    const float* __restrict__ A_v, const float* __restrict__ dec_Wih,
    const int* __restrict__ src_lengths, const int* __restrict__ tgt_lengths)
{
    float4* sW1 = sdyn;          // 2048 f4 = 32KB: [jj 0..15][k4 0..127]
    float4* sW3 = sdyn + 2048;   // 3072 f4 = 48KB: [gate][wj 0..3][k4 0..255]
    float4* sHC = sdyn + 5120;   // 8192 f4 = 128KB: h stage (first 4096) / cT stage (8192)
    __shared__ float se[S];
    int tid = threadIdx.x, lane = tid & 31, w = tid >> 5, bx = blockIdx.x;

    // fill phase-1 weights (dec_Whh rows or A_W rows)
    for (int idx = tid; idx < 2048; idx += 128) {
        int jj = idx >> 7, k4 = idx & 127;
        int j = bx * 16 + jj;
        const float* src = (j < G3) ? (dec_Whh + (size_t)j * H) : (A_W + (size_t)(j - G3) * H);
        sW1[idx] = ((const float4*)src)[k4];
    }
    // fill phase-3 weights (dec_Wih context columns)
    for (int idx = tid; idx < 3072; idx += 128) {
        int g = idx >> 10, rem = idx & 1023, wj = rem >> 8, k4 = rem & 255;
        sW3[idx] = ((const float4*)(dec_Wih + (size_t)(g * 512 + bx * 4 + wj) * G3 + 512))[k4];
    }
    bool is_att = (bx >= 96);
    float bias1[4];
#pragma unroll
    for (int q = 0; q < 4; q++) {
        int j = bx * 16 + w * 4 + q;
        bias1[q] = is_att ? A_b[j - G3] : dec_bhh[j];
    }
    int b2 = bx & 31, q2 = bx >> 5;
    int len2 = src_lengths[b2];
    float av[16];
#pragma unroll
    for (int m = 0; m < 16; m++) av[m] = A_v[lane + m * 32];
    int jh = bx * 4 + w;
    int mylen = tgt_lengths[lane];
    const float4* b1 = sW1 + (w * 4) * 128;
    const float4* b3 = sW3 + w * 256;
    unsigned bt = 0;

    for (int i = 0; i < T; i++) {
        // ---- phase 1: gh = h@Whh^T ; Ah = h@A_W^T ----
        {
            const float* hin = g_hTd[i & 1];
            __syncthreads();
            for (int idx = tid; idx < 4096; idx += 128)
                sHC[idx] = ((const float4*)hin)[idx];
            __syncthreads();
            float a0 = bias1[0], a1 = bias1[1], a2 = bias1[2], a3 = bias1[3];
#pragma unroll 4
            for (int k4 = 0; k4 < 128; k4++) {
                float4 h4 = sHC[k4 * B + lane];
                float4 w0 = b1[k4], w1 = b1[k4 + 128], w2 = b1[k4 + 256], w3 = b1[k4 + 384];
                a0 = fmaf(w0.x, h4.x, a0); a0 = fmaf(w0.y, h4.y, a0); a0 = fmaf(w0.z, h4.z, a0); a0 = fmaf(w0.w, h4.w, a0);
                a1 = fmaf(w1.x, h4.x, a1); a1 = fmaf(w1.y, h4.y, a1); a1 = fmaf(w1.z, h4.z, a1); a1 = fmaf(w1.w, h4.w, a1);
                a2 = fmaf(w2.x, h4.x, a2); a2 = fmaf(w2.y, h4.y, a2); a2 = fmaf(w2.z, h4.z, a2); a2 = fmaf(w2.w, h4.w, a2);
                a3 = fmaf(w3.x, h4.x, a3); a3 = fmaf(w3.y, h4.y, a3); a3 = fmaf(w3.z, h4.z, a3); a3 = fmaf(w3.w, h4.w, a3);
            }
            float acc[4] = {a0, a1, a2, a3};
#pragma unroll
            for (int q = 0; q < 4; q++) {
                int j = bx * 16 + w * 4 + q;
                if (!is_att) g_ghd[j * B + lane] = acc[q];
                else g_Ah[lane * H + (j - G3)] = acc[q];
            }
        }
        bar_sync(&g_cnt_dec[0], (++bt) * DEC_BLOCKS);

        // ---- phase 2: scores + softmax + context ----
        {
            float ah[16];
#pragma unroll
            for (int m = 0; m < 16; m++) ah[m] = g_Ah[b2 * H + lane + m * 32];
#pragma unroll
            for (int si = 0; si < 16; si++) {
                int s = w * 16 + si;
                const float* uh = g_Uh + (size_t)(b2 * S + s) * H;
                float p = 0.f;
#pragma unroll
                for (int m = 0; m < 16; m++)
                    p = fmaf(av[m], tanh_fast(uh[lane + m * 32] + ah[m]), p);
#pragma unroll
                for (int off = 16; off; off >>= 1) p += __shfl_xor_sync(0xffffffffu, p, off);
                if (lane == 0) se[s] = (s < len2) ? p : -1e9f;
            }
            __syncthreads();
            if (w == 0) {
                float e0 = se[lane], e1 = se[lane + 32];
                float m = fmaxf(e0, e1);
#pragma unroll
                for (int off = 16; off; off >>= 1) m = fmaxf(m, __shfl_xor_sync(0xffffffffu, m, off));
                float x0 = __expf(e0 - m), x1 = __expf(e1 - m);
                float sm = x0 + x1;
#pragma unroll
                for (int off = 16; off; off >>= 1) sm += __shfl_xor_sync(0xffffffffu, sm, off);
                float inv = 1.0f / sm;
                se[lane] = x0 * inv; se[lane + 32] = x1 * inv;
            }
            __syncthreads();
            int k2 = q2 * 256 + tid * 2;
            const float* sh = g_srchid + (size_t)(b2 * S) * (2 * H) + k2;
            float a0 = 0.f, a1 = 0.f;
#pragma unroll 8
            for (int s = 0; s < S; s++) {
                float2 v = *(const float2*)(sh + (size_t)s * (2 * H));
                float al = se[s];
                a0 = fmaf(al, v.x, a0); a1 = fmaf(al, v.y, a1);
            }
            int cidx = (k2 >> 2) * (B * 4) + b2 * 4 + (k2 & 3);
            g_cT[cidx] = a0; g_cT[cidx + 1] = a1;
        }
        bar_sync(&g_cnt_dec[0], (++bt) * DEC_BLOCKS);

        // ---- phase 3: gx_c = c@Wih_c^T, gates, h update ----
        {
            __syncthreads();
            for (int idx = tid; idx < 8192; idx += 128)
                sHC[idx] = ((const float4*)g_cT)[idx];
            __syncthreads();
            float ar = 0.f, az = 0.f, an = 0.f;
#pragma unroll 4
            for (int k4 = 0; k4 < 256; k4++) {
                float4 c4 = sHC[k4 * B + lane];
                float4 r4 = b3[k4], z4 = b3[k4 + 1024], n4 = b3[k4 + 2048];
                ar = fmaf(r4.x, c4.x, ar); ar = fmaf(r4.y, c4.y, ar); ar = fmaf(r4.z, c4.z, ar); ar = fmaf(r4.w, c4.w, ar);
                az = fmaf(z4.x, c4.x, az); az = fmaf(z4.y, c4.y, az); az = fmaf(z4.z, c4.z, az); az = fmaf(z4.w, c4.w, az);
                an = fmaf(n4.x, c4.x, an); an = fmaf(n4.y, c4.y, an); an = fmaf(n4.z, c4.z, an); an = fmaf(n4.w, c4.w, an);
            }
            const float* gxt = g_gxemb + (size_t)i * G3 * B;
            float gxr = gxt[(size_t)jh * B + lane] + ar;
            float gxz = gxt[(size_t)(512 + jh) * B + lane] + az;
            float gxn = gxt[(size_t)(1024 + jh) * B + lane] + an;
            float ghr = g_ghd[jh * B + lane];
            float ghz = g_ghd[(512 + jh) * B + lane];
            float ghn = g_ghd[(1024 + jh) * B + lane];
            float r = sigm(gxr + ghr);
            float z = sigm(gxz + ghz);
            float n = tanhf(gxn + r * ghn);
            int hidx = (jh >> 2) * (B * 4) + lane * 4 + (jh & 3);
            float hprev = g_hTd[i & 1][hidx];
            float hnew = (1.f - z) * n + z * hprev;
            int mask = i < mylen;
            g_hTd[(i + 1) & 1][hidx] = mask ? hnew : hprev;
            g_decout[(size_t)(lane * T + i) * H + jh] = mask ? hnew : 0.f;
        }
        if (i < T - 1) bar_sync(&g_cnt_dec[0], (++bt) * DEC_BLOCKS);
    }
}

// ---------------- fp32 -> bf16 ----------------
__global__ __launch_bounds__(256) void cvt_bf16(const float* __restrict__ src,
                                                __nv_bfloat16* __restrict__ dst, int n8)
{
    int i = blockIdx.x * 256 + threadIdx.x;
    if (i < n8) {
        float4 a = ((const float4*)src)[i * 2], b = ((const float4*)src)[i * 2 + 1];
        __nv_bfloat162 o[4];
        o[0] = __nv_bfloat162(__float2bfloat16(a.x), __float2bfloat16(a.y));
        o[1] = __nv_bfloat162(__float2bfloat16(a.z), __float2bfloat16(a.w));
        o[2] = __nv_bfloat162(__float2bfloat16(b.x), __float2bfloat16(b.y));
        o[3] = __nv_bfloat162(__float2bfloat16(b.z), __float2bfloat16(b.w));
        ((uint4*)dst)[i] = *(uint4*)o;
    }
}

// ---------------- bf16 tensor-core logits GEMM ----------------
#define LBM 128
#define LBN 128
#define LBK 32
#define LPAD 8
__device__ __forceinline__ void mma16816(float* d, const unsigned* a, const unsigned* b) {
    asm volatile("mma.sync.aligned.m16n8k16.row.col.f32.bf16.bf16.f32 "
        "{%0,%1,%2,%3},{%4,%5,%6,%7},{%8,%9},{%0,%1,%2,%3};"
        : "+f"(d[0]), "+f"(d[1]), "+f"(d[2]), "+f"(d[3])
        : "r"(a[0]), "r"(a[1]), "r"(a[2]), "r"(a[3]), "r"(b[0]), "r"(b[1]));
}
__global__ __launch_bounds__(256) void gemm_logits(const float* __restrict__ out_b)
{
    __shared__ __nv_bfloat16 As[LBM][LBK + LPAD];
    __shared__ __nv_bfloat16 Ws[LBN][LBK + LPAD];
    int tid = threadIdx.x;
    int m0 = blockIdx.y * LBM, n0 = blockIdx.x * LBN;
    int wid = tid >> 5, lane = tid & 31;
    int wm = (wid & 1) * 64, wn = (wid >> 1) * 32;
    float acc[4][4][4];
#pragma unroll
    for (int a = 0; a < 4; a++)
#pragma unroll
        for (int b = 0; b < 4; b++)
#pragma unroll
            for (int c = 0; c < 4; c++) acc[a][b][c] = 0.f;

    int lr = tid >> 1, lc = (tid & 1) * 16;
    for (int k0 = 0; k0 < H; k0 += LBK) {
        uint4 va  = *(const uint4*)(g_abf + (size_t)(m0 + lr) * H + k0 + lc);
        uint4 va2 = *(const uint4*)(g_abf + (size_t)(m0 + lr) * H + k0 + lc + 8);
        uint4 vw  = *(const uint4*)(g_wbf + (size_t)(n0 + lr) * H + k0 + lc);
        uint4 vw2 = *(const uint4*)(g_wbf + (size_t)(n0 + lr) * H + k0 + lc + 8);
        __syncthreads();
        *(uint4*)&As[lr][lc] = va;  *(uint4*)&As[lr][lc + 8] = va2;
        *(uint4*)&Ws[lr][lc] = vw;  *(uint4*)&Ws[lr][lc + 8] = vw2;
        __syncthreads();
#pragma unroll
        for (int kk = 0; kk < LBK; kk += 16) {
            unsigned af[4][4], bfr[4][2];
            int arow = lane >> 2, acol = kk + (lane & 3) * 2;
#pragma unroll
            for (int mf = 0; mf < 4; mf++) {
                af[mf][0] = *(const unsigned*)&As[wm + mf * 16 + arow][acol];
                af[mf][1] = *(const unsigned*)&As[wm + mf * 16 + arow + 8][acol];
                af[mf][2] = *(const unsigned*)&As[wm + mf * 16 + arow][acol + 8];
                af[mf][3] = *(const unsigned*)&As[wm + mf * 16 + arow + 8][acol + 8];
            }
#pragma unroll
            for (int nf = 0; nf < 4; nf++) {
                int brow = wn + nf * 8 + (lane >> 2);
                bfr[nf][0] = *(const unsigned*)&Ws[brow][acol];
                bfr[nf][1] = *(const unsigned*)&Ws[brow][acol + 8];
            }
#pragma unroll
            for (int mf = 0; mf < 4; mf++)
#pragma unroll
                for (int nf = 0; nf < 4; nf++) mma16816(acc[mf][nf], af[mf], bfr[nf]);
        }
    }
#pragma unroll
    for (int mf = 0; mf < 4; mf++)
#pragma unroll
        for (int nf = 0; nf < 4; nf++) {
            int m = m0 + wm + mf * 16 + (lane >> 2);
            int n = n0 + wn + nf * 8 + (lane & 3) * 2;
            float b0 = out_b[n], b1 = out_b[n + 1];
            float* p = g_logits + (size_t)m * V + n;
            p[0] = acc[mf][nf][0] + b0; p[1] = acc[mf][nf][1] + b1;
            float* p2 = p + (size_t)8 * V;
            p2[0] = acc[mf][nf][2] + b0; p2[1] = acc[mf][nf][3] + b1;
        }
}

// ---------------- online logsumexp per row ----------------
__global__ __launch_bounds__(256) void row_lse(const int* __restrict__ tgt_seqs)
{
    int row = blockIdx.x, b = row / T, t = row % T;
    const float* lg = g_logits + (size_t)row * V;
    int tid = threadIdx.x;
    float m = -1e30f, s = 0.f;
    for (int v = tid; v < V; v += 256) {
        float x = lg[v];
        if (x > m) { s = s * __expf(m - x) + 1.f; m = x; }
        else s += __expf(x - m);
    }
    __shared__ float sm_[256], ss_[256];
    sm_[tid] = m; ss_[tid] = s; __syncthreads();
    for (int q = 128; q; q >>= 1) {
        if (tid < q) {
            float m1 = sm_[tid], s1 = ss_[tid], m2 = sm_[tid + q], s2 = ss_[tid + q];
            float mm = fmaxf(m1, m2);
            sm_[tid] = mm; ss_[tid] = s1 * __expf(m1 - mm) + s2 * __expf(m2 - mm);
        }
        __syncthreads();
    }
    if (tid == 0) {
        int goal = (t < T - 1) ? tgt_seqs[b * T + t + 1] : 0;
        float lse = sm_[0] + logf(ss_[0]);
        g_rowres[row] = (goal != 0) ? (lg[goal] - lse) : 0.f;
    }
}

__global__ __launch_bounds__(256) void final_loss(
    const int* __restrict__ tgt_seqs, float* __restrict__ out)
{
    __shared__ float sp[256], sc[256];
    int tid = threadIdx.x;
    float ps = 0.f, pc = 0.f;
    for (int r = tid; r < B * T; r += 256) {
        ps += g_rowres[r];
        int b = r / T, t = r % T;
        int goal = (t < T - 1) ? tgt_seqs[b * T + t + 1] : 0;
        pc += (goal != 0) ? 1.f : 0.f;
    }
    sp[tid] = ps; sc[tid] = pc; __syncthreads();
    for (int q = 128; q; q >>= 1) {
        if (tid < q) { sp[tid] += sp[tid + q]; sc[tid] += sc[tid + q]; }
        __syncthreads();
    }
    if (tid == 0) out[0] = -sp[0] / sc[0];
}

extern "C" void kernel_launch(void* const* d_in, const int* in_sizes, int n_in,
                              void* d_out, int out_size)
{
    const int* src_seqs    = (const int*)d_in[0];
    const int* src_lengths = (const int*)d_in[1];
    const int* tgt_seqs    = (const int*)d_in[2];
    const int* tgt_lengths = (const int*)d_in[3];
    const float* src_emb   = (const float*)d_in[4];
    const float* enc_Wih_f = (const float*)d_in[5];
    const float* enc_Whh_f = (const float*)d_in[6];
    const float* enc_bih_f = (const float*)d_in[7];
    const float* enc_bhh_f = (const float*)d_in[8];
    const float* enc_Wih_b = (const float*)d_in[9];
    const float* enc_Whh_b = (const float*)d_in[10];
    const float* enc_bih_b = (const float*)d_in[11];
    const float* enc_bhh_b = (const float*)d_in[12];
    const float* tgt_emb   = (const float*)d_in[13];
    const float* dec_Wih   = (const float*)d_in[14];
    const float* dec_Whh   = (const float*)d_in[15];
    const float* dec_bih   = (const float*)d_in[16];
    const float* dec_bhh   = (const float*)d_in[17];
    const float* U_w       = (const float*)d_in[18];
    const float* U_b       = (const float*)d_in[19];
    const float* A_W       = (const float*)d_in[20];
    const float* A_b       = (const float*)d_in[21];
    const float* A_v       = (const float*)d_in[22];
    const float* out_w     = (const float*)d_in[23];
    const float* out_b     = (const float*)d_in[24];

    void *p_esrc, *p_etgt, *p_gxf, *p_gxb, *p_gxemb, *p_srchid, *p_Uh, *p_decout, *p_wbf, *p_abf;
    cudaGetSymbolAddress(&p_esrc, g_esrc);
    cudaGetSymbolAddress(&p_etgt, g_etgt);
    cudaGetSymbolAddress(&p_gxf, g_gxf);
    cudaGetSymbolAddress(&p_gxb, g_gxb);
    cudaGetSymbolAddress(&p_gxemb, g_gxemb);
    cudaGetSymbolAddress(&p_srchid, g_srchid);
    cudaGetSymbolAddress(&p_Uh, g_Uh);
    cudaGetSymbolAddress(&p_decout, g_decout);
    cudaGetSymbolAddress(&p_wbf, g_wbf);
    cudaGetSymbolAddress(&p_abf, g_abf);

    const int enc_smem = (3072 + 4096) * 16;            // 114688 B
    const int dec_smem = (2048 + 3072 + 8192) * 16;     // 212992 B
    cudaFuncSetAttribute(enc_persist, cudaFuncAttributeMaxDynamicSharedMemorySize, enc_smem);
    cudaFuncSetAttribute(dec_persist, cudaFuncAttributeMaxDynamicSharedMemorySize, dec_smem);

    zero_h_kernel<<<(H * B + 255) / 256, 256>>>();
    embed_kernel<<<B * S + B * T, 128>>>(src_seqs, tgt_seqs, src_emb, tgt_emb);

    gemm_nt<1><<<dim3(G3 / GBN, (B * S) / GBM), 256>>>(
        (const float*)p_esrc, E, enc_Wih_f, E, enc_bih_f, (float*)p_gxf, G3, E, S);
    gemm_nt<1><<<dim3(G3 / GBN, (B * S) / GBM), 256>>>(
        (const float*)p_esrc, E, enc_Wih_b, E, enc_bih_b, (float*)p_gxb, G3, E, S);
    gemm_nt<1><<<dim3(G3 / GBN, (B * T) / GBM), 256>>>(
        (const float*)p_etgt, E, dec_Wih, G3, dec_bih, (float*)p_gxemb, G3, E, T);

    enc_persist<<<ENC_BLOCKS, 128, enc_smem>>>(enc_Whh_f, enc_bhh_f, enc_Whh_b, enc_bhh_b, src_lengths);

    gemm_nt<0><<<dim3(H / GBN, (B * S) / GBM), 256>>>(
        (const float*)p_srchid, 2 * H, U_w, 2 * H, U_b, (float*)p_Uh, H, 2 * H, S);

    dec_persist<<<DEC_BLOCKS, 128, dec_smem>>>(dec_Whh, dec_bhh, A_W, A_b, A_v, dec_Wih,
                                               src_lengths, tgt_lengths);

    cvt_bf16<<<(B * T * H / 8 + 255) / 256, 256>>>((const float*)p_decout,
                                                   (__nv_bfloat16*)p_abf, B * T * H / 8);
    cvt_bf16<<<((int)((size_t)V * H / 8) + 255) / 256, 256>>>(out_w,
                                                   (__nv_bfloat16*)p_wbf, (int)((size_t)V * H / 8));

    gemm_logits<<<dim3(V / LBN, (B * T) / LBM), 256>>>(out_b);

    row_lse<<<B * T, 256>>>(tgt_seqs);
    final_loss<<<1, 256>>>(tgt_seqs, (float*)d_out);
}

// round 12
// speedup vs baseline: 3.8320x; 1.0169x over previous
#include <cuda_runtime.h>
#include <cuda_bf16.h>
#include <math.h>

#define B 32
#define S 64
#define T 64
#define E 512
#define H 512
#define V 32000
#define G3 1536
#define NB 250          // V / 128 partial blocks

#define ENC_BLOCKS 128
#define DEC_BLOCKS 128

__device__ float g_esrc[B * S * E];
__device__ float g_etgt[B * T * E];
__device__ float g_gxf[B * S * G3];          // [t][j][b]
__device__ float g_gxb[B * S * G3];
__device__ float g_gxemb[B * T * G3];        // [i][j][b]
__device__ float g_srchid[B * S * 2 * H];    // [b][s][2H]
__device__ float g_Uh[B * S * H];
__device__ float g_P[(size_t)B * G3 * S];    // [b][j][s]
__device__ float g_hTf[2][H * B];            // float4 layout: f4 idx k4*B+b
__device__ float g_hTb[2][H * B];
__device__ float g_hTd[2][H * B];
__device__ float g_Ah[B * H];
__device__ float g_alpha[B * S];
__device__ float g_decout[B * T * H];
__device__ float g_pm[B * T * NB];
__device__ float g_ps[B * T * NB];
__device__ float g_rowres[B * T];
__device__ float g_zb[G3];
__device__ __nv_bfloat16 g_wbf[(size_t)V * H];
__device__ __nv_bfloat16 g_abf[B * T * H];
__device__ unsigned g_cnt_enc[32];
__device__ unsigned g_cnt_dec[32];

__device__ __forceinline__ float sigm(float x) { return 1.0f / (1.0f + expf(-x)); }
__device__ __forceinline__ float tanh_fast(float x) {
    float y; asm("tanh.approx.f32 %0, %1;" : "=f"(y) : "f"(x)); return y;
}
__device__ __forceinline__ void bar_sync(unsigned* cnt, unsigned target) {
    __syncthreads();
    if (threadIdx.x == 0) {
        asm volatile("fence.acq_rel.gpu;" ::: "memory");
        asm volatile("red.relaxed.gpu.add.u32 [%0], 1;" :: "l"(cnt) : "memory");
        unsigned v;
        do {
            asm volatile("ld.relaxed.gpu.u32 %0, [%1];" : "=r"(v) : "l"(cnt) : "memory");
        } while (v < target);
        asm volatile("fence.acq_rel.gpu;" ::: "memory");
    }
    __syncthreads();
}

__global__ void zero_h_kernel() {
    int idx = blockIdx.x * blockDim.x + threadIdx.x;
    if (idx < H * B) { g_hTf[0][idx] = 0.f; g_hTb[0][idx] = 0.f; g_hTd[0][idx] = 0.f; }
    if (idx < G3) g_zb[idx] = 0.f;
    if (idx == 0) { g_cnt_enc[0] = 0; g_cnt_dec[0] = 0; }
}

__global__ __launch_bounds__(128) void embed_kernel(
    const int* __restrict__ src_seqs, const int* __restrict__ tgt_seqs,
    const float* __restrict__ src_emb, const float* __restrict__ tgt_emb)
{
    int blk = blockIdx.x, tid = threadIdx.x;
    if (blk < B * S) {
        int tok = src_seqs[blk];
        ((float4*)(g_esrc + (size_t)blk * E))[tid] = ((const float4*)(src_emb + (size_t)tok * E))[tid];
    } else {
        int r = blk - B * S;
        int tok = tgt_seqs[r];
        ((float4*)(g_etgt + (size_t)r * E))[tid] = ((const float4*)(tgt_emb + (size_t)tok * E))[tid];
    }
}

// ---- fp32 GEMM: C=A@W^T+bias; TR=0 row-major, TR=1 [s][n][b], TR=2 [b][n][s] ----
#define GBM 128
#define GBN 64
#define GBK 16
template<int TR>
__global__ __launch_bounds__(256) void gemm_nt(
    const float* __restrict__ A, int lda,
    const float* __restrict__ W, int ldw,
    const float* __restrict__ bias,
    float* __restrict__ C, int ldc, int K, int sdim)
{
    __shared__ float As[GBK][GBM];
    __shared__ float Bs[GBK][GBN];
    int tid = threadIdx.x;
    int m0 = blockIdx.y * GBM, n0 = blockIdx.x * GBN;
    int tx = tid & 15, ty = tid >> 4;
    float acc[8][4];
#pragma unroll
    for (int i = 0; i < 8; i++)
#pragma unroll
        for (int j = 0; j < 4; j++) acc[i][j] = 0.f;
    int ar0 = tid >> 2, ak0 = (tid & 3) * 4;
    for (int k0 = 0; k0 < K; k0 += GBK) {
#pragma unroll
        for (int h = 0; h < 2; h++) {
            int r = ar0 + h * 64;
            float4 v = *(const float4*)(A + (size_t)(m0 + r) * lda + k0 + ak0);
            As[ak0 + 0][r] = v.x; As[ak0 + 1][r] = v.y; As[ak0 + 2][r] = v.z; As[ak0 + 3][r] = v.w;
        }
        {
            float4 v = *(const float4*)(W + (size_t)(n0 + ar0) * ldw + k0 + ak0);
            Bs[ak0 + 0][ar0] = v.x; Bs[ak0 + 1][ar0] = v.y; Bs[ak0 + 2][ar0] = v.z; Bs[ak0 + 3][ar0] = v.w;
        }
        __syncthreads();
#pragma unroll
        for (int kk = 0; kk < GBK; kk++) {
            float a[8], b[4];
#pragma unroll
            for (int i = 0; i < 8; i++) a[i] = As[kk][ty * 8 + i];
#pragma unroll
            for (int j = 0; j < 4; j++) b[j] = Bs[kk][tx * 4 + j];
#pragma unroll
            for (int i = 0; i < 8; i++)
#pragma unroll
                for (int j = 0; j < 4; j++) acc[i][j] = fmaf(a[i], b[j], acc[i][j]);
        }
        __syncthreads();
    }
    float b4[4];
#pragma unroll
    for (int j = 0; j < 4; j++) b4[j] = bias[n0 + tx * 4 + j];
#pragma unroll
    for (int i = 0; i < 8; i++) {
        int m = m0 + ty * 8 + i;
        if (TR == 1) {
            int bb = m / sdim, s = m % sdim;
#pragma unroll
            for (int j = 0; j < 4; j++)
                C[((size_t)s * G3 + n0 + tx * 4 + j) * B + bb] = acc[i][j] + b4[j];
        } else if (TR == 2) {
            int bb = m / sdim, s = m % sdim;
#pragma unroll
            for (int j = 0; j < 4; j++)
                C[((size_t)bb * G3 + n0 + tx * 4 + j) * sdim + s] = acc[i][j] + b4[j];
        } else {
            float4 o;
            o.x = acc[i][0] + b4[0]; o.y = acc[i][1] + b4[1];
            o.z = acc[i][2] + b4[2]; o.w = acc[i][3] + b4[3];
            *(float4*)(C + (size_t)m * ldc + n0 + tx * 4) = o;
        }
    }
}

// ---------------- persistent encoder (R9-proven) ----------------
extern __shared__ float4 sdyn[];
__global__ __launch_bounds__(128) void enc_persist(
    const float* __restrict__ Whh_f, const float* __restrict__ bhh_f,
    const float* __restrict__ Whh_b, const float* __restrict__ bhh_b,
    const int* __restrict__ src_lengths)
{
    float4* sW = sdyn;
    float4* sH = sdyn + 3072;
    int tid = threadIdx.x, lane = tid & 31, w = tid >> 5, bx = blockIdx.x;
    int dir = bx >> 6, j0c = (bx & 63) * 8;
    const float* Whh = dir ? Whh_b : Whh_f;
    const float* bhh = dir ? bhh_b : bhh_f;
    const float* gx = dir ? g_gxb : g_gxf;
    float* hbuf0 = dir ? g_hTb[0] : g_hTf[0];
    float* hbuf1 = dir ? g_hTb[1] : g_hTf[1];
    int len = src_lengths[lane];

    for (int idx = tid; idx < 3072; idx += 128) {
        int g = idx >> 10, rem = idx & 1023, jj = rem >> 7, k4 = rem & 127;
        sW[idx] = ((const float4*)(Whh + (size_t)(g * H + j0c + jj) * H))[k4];
    }
    int jj0 = w * 2, j0 = j0c + jj0;
    float br0 = bhh[j0],     bz0 = bhh[H + j0],     bn0 = bhh[2 * H + j0];
    float br1 = bhh[j0 + 1], bz1 = bhh[H + j0 + 1], bn1 = bhh[2 * H + j0 + 1];
    const float4* base = sW + jj0 * 128;
    unsigned bt = 0;

    for (int i = 0; i < S; i++) {
        int t = dir ? (S - 1 - i) : i;
        const float* hin = (i & 1) ? hbuf1 : hbuf0;
        float* hout = (i & 1) ? hbuf0 : hbuf1;
        __syncthreads();
        for (int idx = tid; idx < 4096; idx += 128)
            sH[idx] = ((const float4*)hin)[idx];
        __syncthreads();

        float ar0 = br0, az0 = bz0, an0 = bn0, ar1 = br1, az1 = bz1, an1 = bn1;
#pragma unroll 4
        for (int k4 = 0; k4 < 128; k4++) {
            float4 h4 = sH[k4 * B + lane];
            float4 r0 = base[k4],        r1 = base[k4 + 128];
            float4 z0 = base[k4 + 1024], z1 = base[k4 + 1152];
            float4 n0 = base[k4 + 2048], n1 = base[k4 + 2176];
            ar0 = fmaf(r0.x, h4.x, ar0); ar0 = fmaf(r0.y, h4.y, ar0); ar0 = fmaf(r0.z, h4.z, ar0); ar0 = fmaf(r0.w, h4.w, ar0);
            ar1 = fmaf(r1.x, h4.x, ar1); ar1 = fmaf(r1.y, h4.y, ar1); ar1 = fmaf(r1.z, h4.z, ar1); ar1 = fmaf(r1.w, h4.w, ar1);
            az0 = fmaf(z0.x, h4.x, az0); az0 = fmaf(z0.y, h4.y, az0); az0 = fmaf(z0.z, h4.z, az0); az0 = fmaf(z0.w, h4.w, az0);
            az1 = fmaf(z1.x, h4.x, az1); az1 = fmaf(z1.y, h4.y, az1); az1 = fmaf(z1.z, h4.z, az1); az1 = fmaf(z1.w, h4.w, az1);
            an0 = fmaf(n0.x, h4.x, an0); an0 = fmaf(n0.y, h4.y, an0); an0 = fmaf(n0.z, h4.z, an0); an0 = fmaf(n0.w, h4.w, an0);
            an1 = fmaf(n1.x, h4.x, an1); an1 = fmaf(n1.y, h4.y, an1); an1 = fmaf(n1.z, h4.z, an1); an1 = fmaf(n1.w, h4.w, an1);
        }
        int mask = t < len;
        const float* gxt = gx + (size_t)t * G3 * B;
#pragma unroll
        for (int jj = 0; jj < 2; jj++) {
            int j = j0 + jj;
            float ar = jj ? ar1 : ar0, az = jj ? az1 : az0, an = jj ? an1 : an0;
            float r = sigm(gxt[(size_t)j * B + lane] + ar);
            float z = sigm(gxt[(size_t)(H + j) * B + lane] + az);
            float n = tanhf(gxt[(size_t)(2 * H + j) * B + lane] + r * an);
            int hidx = (j >> 2) * (B * 4) + lane * 4 + (j & 3);
            float hprev = ((const float*)sH)[hidx];
            float hnew = (1.f - z) * n + z * hprev;
            hout[hidx] = mask ? hnew : hprev;
            g_srchid[(size_t)(lane * S + t) * (2 * H) + dir * H + j] = mask ? hnew : 0.f;
        }
        if (i < S - 1) bar_sync(&g_cnt_enc[0], (++bt) * ENC_BLOCKS);
    }
}

// ---------------- persistent decoder with P-trick ----------------
__global__ __launch_bounds__(128) void dec_persist(
    const float* __restrict__ dec_Whh, const float* __restrict__ dec_bhh,
    const float* __restrict__ A_W, const float* __restrict__ A_b,
    const float* __restrict__ A_v,
    const int* __restrict__ src_lengths, const int* __restrict__ tgt_lengths)
{
    float4* sW1 = sdyn;            // 2048 f4 = 32KB: slots 0-3 r, 4-7 z, 8-11 n, 12-15 A_W
    float4* sH  = sdyn + 2048;     // 4096 f4 = 64KB
    __shared__ float se[S];
    __shared__ float sAl[S * 33];
    int tid = threadIdx.x, lane = tid & 31, w = tid >> 5, bx = blockIdx.x;
    int jh = bx * 4 + w;

    for (int idx = tid; idx < 2048; idx += 128) {
        int slot = idx >> 7, k4 = idx & 127;
        const float* src;
        if (slot < 12) src = dec_Whh + (size_t)((slot >> 2) * 512 + bx * 4 + (slot & 3)) * H;
        else           src = A_W + (size_t)(bx * 4 + (slot - 12)) * H;
        sW1[idx] = ((const float4*)src)[k4];
    }
    float bhr = dec_bhh[jh], bhz = dec_bhh[512 + jh], bhn = dec_bhh[1024 + jh];
    float ba  = A_b[jh];
    int len2 = src_lengths[bx & 31];
    float av[16];
#pragma unroll
    for (int m = 0; m < 16; m++) av[m] = A_v[lane + m * 32];
    int mylen = tgt_lengths[lane];
    const float4* wR = sW1 + (0 + w) * 128;
    const float4* wZ = sW1 + (4 + w) * 128;
    const float4* wN = sW1 + (8 + w) * 128;
    const float4* wA = sW1 + (12 + w) * 128;
    const float* Pr = g_P + ((size_t)lane * G3 + jh) * S;
    const float* Pz = Pr + (size_t)512 * S;
    const float* Pn = Pr + (size_t)1024 * S;
    unsigned bt = 0;

    for (int i = 0; i < T; i++) {
        float ghr, ghz, ghn;
        // ---- phase A: gh (regs) + Ah ----
        {
            const float* hin = g_hTd[i & 1];
            __syncthreads();
            for (int idx = tid; idx < 4096; idx += 128)
                sH[idx] = ((const float4*)hin)[idx];
            __syncthreads();
            float aR = bhr, aZ = bhz, aN = bhn, aA = ba;
#pragma unroll 4
            for (int k4 = 0; k4 < 128; k4++) {
                float4 h4 = sH[k4 * B + lane];
                float4 r4 = wR[k4], z4 = wZ[k4], n4 = wN[k4], a4 = wA[k4];
                aR = fmaf(r4.x, h4.x, aR); aR = fmaf(r4.y, h4.y, aR); aR = fmaf(r4.z, h4.z, aR); aR = fmaf(r4.w, h4.w, aR);
                aZ = fmaf(z4.x, h4.x, aZ); aZ = fmaf(z4.y, h4.y, aZ); aZ = fmaf(z4.z, h4.z, aZ); aZ = fmaf(z4.w, h4.w, aZ);
                aN = fmaf(n4.x, h4.x, aN); aN = fmaf(n4.y, h4.y, aN); aN = fmaf(n4.z, h4.z, aN); aN = fmaf(n4.w, h4.w, aN);
                aA = fmaf(a4.x, h4.x, aA); aA = fmaf(a4.y, h4.y, aA); aA = fmaf(a4.z, h4.z, aA); aA = fmaf(a4.w, h4.w, aA);
            }
            ghr = aR; ghz = aZ; ghn = aN;
            g_Ah[lane * H + jh] = aA;
        }
        bar_sync(&g_cnt_dec[0], (++bt) * DEC_BLOCKS);

        // ---- phase B (CTAs 0..31): scores + softmax -> alpha ----
        if (bx < 32) {
            int b2 = bx;
            float ah[16];
#pragma unroll
            for (int m = 0; m < 16; m++) ah[m] = g_Ah[b2 * H + lane + m * 32];
#pragma unroll
            for (int si = 0; si < 16; si++) {
                int s = w * 16 + si;
                const float* uh = g_Uh + (size_t)(b2 * S + s) * H;
                float p = 0.f;
#pragma unroll
                for (int m = 0; m < 16; m++)
                    p = fmaf(av[m], tanh_fast(uh[lane + m * 32] + ah[m]), p);
#pragma unroll
                for (int off = 16; off; off >>= 1) p += __shfl_xor_sync(0xffffffffu, p, off);
                if (lane == 0) se[s] = (s < len2) ? p : -1e9f;
            }
            __syncthreads();
            if (w == 0) {
                float e0 = se[lane], e1 = se[lane + 32];
                float m = fmaxf(e0, e1);
#pragma unroll
                for (int off = 16; off; off >>= 1) m = fmaxf(m, __shfl_xor_sync(0xffffffffu, m, off));
                float x0 = __expf(e0 - m), x1 = __expf(e1 - m);
                float sm = x0 + x1;
#pragma unroll
                for (int off = 16; off; off >>= 1) sm += __shfl_xor_sync(0xffffffffu, sm, off);
                float inv = 1.0f / sm;
                g_alpha[b2 * S + lane] = x0 * inv;
                g_alpha[b2 * S + lane + 32] = x1 * inv;
            }
        }
        bar_sync(&g_cnt_dec[0], (++bt) * DEC_BLOCKS);

        // ---- phase C: gx_c via P, gates, h update ----
        {
            for (int idx = tid; idx < B * S; idx += 128) {
                int s = idx >> 5, b = idx & 31;
                sAl[s * 33 + b] = g_alpha[b * S + s];
            }
            __syncthreads();
            float ar = 0.f, az = 0.f, an = 0.f;
#pragma unroll 8
            for (int s = 0; s < S; s++) {
                float a = sAl[s * 33 + lane];
                ar = fmaf(a, Pr[s], ar);
                az = fmaf(a, Pz[s], az);
                an = fmaf(a, Pn[s], an);
            }
            const float* gxt = g_gxemb + (size_t)i * G3 * B;
            float gxr = gxt[(size_t)jh * B + lane] + ar;
            float gxz = gxt[(size_t)(512 + jh) * B + lane] + az;
            float gxn = gxt[(size_t)(1024 + jh) * B + lane] + an;
            float r = sigm(gxr + ghr);
            float z = sigm(gxz + ghz);
            float n = tanhf(gxn + r * ghn);
            int hidx = (jh >> 2) * (B * 4) + lane * 4 + (jh & 3);
            float hprev = g_hTd[i & 1][hidx];
            float hnew = (1.f - z) * n + z * hprev;
            int mask = i < mylen;
            g_hTd[(i + 1) & 1][hidx] = mask ? hnew : hprev;
            g_decout[(size_t)(lane * T + i) * H + jh] = mask ? hnew : 0.f;
            __syncthreads();
        }
        if (i < T - 1) bar_sync(&g_cnt_dec[0], (++bt) * DEC_BLOCKS);
    }
}

__global__ __launch_bounds__(256) void cvt_bf16(const float* __restrict__ src,
                                                __nv_bfloat16* __restrict__ dst, int n8)
{
    int i = blockIdx.x * 256 + threadIdx.x;
    if (i < n8) {
        float4 a = ((const float4*)src)[i * 2], b = ((const float4*)src)[i * 2 + 1];
        __nv_bfloat162 o[4];
        o[0] = __nv_bfloat162(__float2bfloat16(a.x), __float2bfloat16(a.y));
        o[1] = __nv_bfloat162(__float2bfloat16(a.z), __float2bfloat16(a.w));
        o[2] = __nv_bfloat162(__float2bfloat16(b.x), __float2bfloat16(b.y));
        o[3] = __nv_bfloat162(__float2bfloat16(b.z), __float2bfloat16(b.w));
        ((uint4*)dst)[i] = *(uint4*)o;
    }
}

// ---------------- bf16 mma logits GEMM fused with per-tile online LSE ----------------
#define LBM 128
#define LBN 128
#define LBK 32
#define LPAD 8
__device__ __forceinline__ void mma16816(float* d, const unsigned* a, const unsigned* b) {
    asm volatile("mma.sync.aligned.m16n8k16.row.col.f32.bf16.bf16.f32 "
        "{%0,%1,%2,%3},{%4,%5,%6,%7},{%8,%9},{%0,%1,%2,%3};"
        : "+f"(d[0]), "+f"(d[1]), "+f"(d[2]), "+f"(d[3])
        : "r"(a[0]), "r"(a[1]), "r"(a[2]), "r"(a[3]), "r"(b[0]), "r"(b[1]));
}
__global__ __launch_bounds__(256) void gemm_logits(const float* __restrict__ out_b)
{
    __shared__ __nv_bfloat16 As[LBM][LBK + LPAD];
    __shared__ __nv_bfloat16 Ws[LBN][LBK + LPAD];
    __shared__ float smM[LBM][4], smS[LBM][4];
    int tid = threadIdx.x;
    int m0 = blockIdx.y * LBM, n0 = blockIdx.x * LBN;
    int wid = tid >> 5, lane = tid & 31;
    int wm = (wid & 1) * 64, wn = (wid >> 1) * 32;
    float acc[4][4][4];
#pragma unroll
    for (int a = 0; a < 4; a++)
#pragma unroll
        for (int b = 0; b < 4; b++)
#pragma unroll
            for (int c = 0; c < 4; c++) acc[a][b][c] = 0.f;

    int lr = tid >> 1, lc = (tid & 1) * 16;
    for (int k0 = 0; k0 < H; k0 += LBK) {
        uint4 va  = *(const uint4*)(g_abf + (size_t)(m0 + lr) * H + k0 + lc);
        uint4 va2 = *(const uint4*)(g_abf + (size_t)(m0 + lr) * H + k0 + lc + 8);
        uint4 vw  = *(const uint4*)(g_wbf + (size_t)(n0 + lr) * H + k0 + lc);
        uint4 vw2 = *(const uint4*)(g_wbf + (size_t)(n0 + lr) * H + k0 + lc + 8);
        __syncthreads();
        *(uint4*)&As[lr][lc] = va;  *(uint4*)&As[lr][lc + 8] = va2;
        *(uint4*)&Ws[lr][lc] = vw;  *(uint4*)&Ws[lr][lc + 8] = vw2;
        __syncthreads();
#pragma unroll
        for (int kk = 0; kk < LBK; kk += 16) {
            unsigned af[4][4], bfr[4][2];
            int arow = lane >> 2, acol = kk + (lane & 3) * 2;
#pragma unroll
            for (int mf = 0; mf < 4; mf++) {
                af[mf][0] = *(const unsigned*)&As[wm + mf * 16 + arow][acol];
                af[mf][1] = *(const unsigned*)&As[wm + mf * 16 + arow + 8][acol];
                af[mf][2] = *(const unsigned*)&As[wm + mf * 16 + arow][acol + 8];
                af[mf][3] = *(const unsigned*)&As[wm + mf * 16 + arow + 8][acol + 8];
            }
#pragma unroll
            for (int nf = 0; nf < 4; nf++) {
                int brow = wn + nf * 8 + (lane >> 2);
                bfr[nf][0] = *(const unsigned*)&Ws[brow][acol];
                bfr[nf][1] = *(const unsigned*)&Ws[brow][acol + 8];
            }
#pragma unroll
            for (int mf = 0; mf < 4; mf++)
#pragma unroll
                for (int nf = 0; nf < 4; nf++) mma16816(acc[mf][nf], af[mf], bfr[nf]);
        }
    }
    // ---- fused per-row online LSE over this 128-col tile ----
    float bb[4][2];
#pragma unroll
    for (int nf = 0; nf < 4; nf++) {
        int n = n0 + wn + nf * 8 + (lane & 3) * 2;
        bb[nf][0] = out_b[n]; bb[nf][1] = out_b[n + 1];
    }
    __syncthreads();
#pragma unroll
    for (int half = 0; half < 2; half++) {
#pragma unroll
        for (int mf = 0; mf < 4; mf++) {
            float m = -1e30f, s = 0.f;
#pragma unroll
            for (int nf = 0; nf < 4; nf++) {
#pragma unroll
                for (int c = 0; c < 2; c++) {
                    float x = acc[mf][nf][half * 2 + c] + bb[nf][c];
                    if (x > m) { s = s * __expf(m - x) + 1.f; m = x; }
                    else s += __expf(x - m);
                }
            }
#pragma unroll
            for (int off = 1; off < 4; off <<= 1) {
                float m2 = __shfl_xor_sync(0xffffffffu, m, off);
                float s2 = __shfl_xor_sync(0xffffffffu, s, off);
                float mm = fmaxf(m, m2);
                s = s * __expf(m - mm) + s2 * __expf(m2 - mm);
                m = mm;
            }
            if ((lane & 3) == 0) {
                int rr = wm + mf * 16 + (lane >> 2) + 8 * half;
                smM[rr][wid >> 1] = m; smS[rr][wid >> 1] = s;
            }
        }
    }
    __syncthreads();
    if (tid < LBM) {
        float m = smM[tid][0], s = smS[tid][0];
#pragma unroll
        for (int q = 1; q < 4; q++) {
            float m2 = smM[tid][q], s2 = smS[tid][q];
            float mm = fmaxf(m, m2);
            s = s * __expf(m - mm) + s2 * __expf(m2 - mm);
            m = mm;
        }
        g_pm[(size_t)(m0 + tid) * NB + blockIdx.x] = m;
        g_ps[(size_t)(m0 + tid) * NB + blockIdx.x] = s;
    }
}

// ---------------- merge partials + picked logit ----------------
__global__ __launch_bounds__(256) void merge_lse(
    const int* __restrict__ tgt_seqs, const float* __restrict__ out_b)
{
    int row = blockIdx.x, b = row / T, t = row % T;
    int tid = threadIdx.x;
    int goal = (t < T - 1) ? tgt_seqs[b * T + t + 1] : 0;
    __shared__ float sm_[256], ss_[256];
    float m = -1e30f, s = 0.f;
    if (tid < NB) { m = g_pm[(size_t)row * NB + tid]; s = g_ps[(size_t)row * NB + tid]; }
    sm_[tid] = m; ss_[tid] = s; __syncthreads();
    for (int q = 128; q; q >>= 1) {
        if (tid < q) {
            float m1 = sm_[tid], s1 = ss_[tid], m2 = sm_[tid + q], s2 = ss_[tid + q];
            float mm = fmaxf(m1, m2);
            sm_[tid] = mm; ss_[tid] = s1 * __expf(m1 - mm) + s2 * __expf(m2 - mm);
        }
        __syncthreads();
    }
    float lse = sm_[0] + logf(ss_[0]);
    // picked logit from same bf16-rounded operands
    float p = 0.f;
    if (goal != 0) {
        for (int k = tid; k < H; k += 256)
            p += __bfloat162float(g_abf[(size_t)row * H + k]) *
                 __bfloat162float(g_wbf[(size_t)goal * H + k]);
    }
    __syncthreads();
    sm_[tid] = p; __syncthreads();
    for (int q = 128; q; q >>= 1) {
        if (tid < q) sm_[tid] += sm_[tid + q];
        __syncthreads();
    }
    if (tid == 0)
        g_rowres[row] = (goal != 0) ? (sm_[0] + out_b[goal] - lse) : 0.f;
}

__global__ __launch_bounds__(256) void final_loss(
    const int* __restrict__ tgt_seqs, float* __restrict__ out)
{
    __shared__ float sp[256], sc[256];
    int tid = threadIdx.x;
    float ps = 0.f, pc = 0.f;
    for (int r = tid; r < B * T; r += 256) {
        ps += g_rowres[r];
        int b = r / T, t = r % T;
        int goal = (t < T - 1) ? tgt_seqs[b * T + t + 1] : 0;
        pc += (goal != 0) ? 1.f : 0.f;
    }
    sp[tid] = ps; sc[tid] = pc; __syncthreads();
    for (int q = 128; q; q >>= 1) {
        if (tid < q) { sp[tid] += sp[tid + q]; sc[tid] += sc[tid + q]; }
        __syncthreads();
    }
    if (tid == 0) out[0] = -sp[0] / sc[0];
}

extern "C" void kernel_launch(void* const* d_in, const int* in_sizes, int n_in,
                              void* d_out, int out_size)
{
    const int* src_seqs    = (const int*)d_in[0];
    const int* src_lengths = (const int*)d_in[1];
    const int* tgt_seqs    = (const int*)d_in[2];
    const int* tgt_lengths = (const int*)d_in[3];
    const float* src_emb   = (const float*)d_in[4];
    const float* enc_Wih_f = (const float*)d_in[5];
    const float* enc_Whh_f = (const float*)d_in[6];
    const float* enc_bih_f = (const float*)d_in[7];
    const float* enc_bhh_f = (const float*)d_in[8];
    const float* enc_Wih_b = (const float*)d_in[9];
    const float* enc_Whh_b = (const float*)d_in[10];
    const float* enc_bih_b = (const float*)d_in[11];
    const float* enc_bhh_b = (const float*)d_in[12];
    const float* tgt_emb   = (const float*)d_in[13];
    const float* dec_Wih   = (const float*)d_in[14];
    const float* dec_Whh   = (const float*)d_in[15];
    const float* dec_bih   = (const float*)d_in[16];
    const float* dec_bhh   = (const float*)d_in[17];
    const float* U_w       = (const float*)d_in[18];
    const float* U_b       = (const float*)d_in[19];
    const float* A_W       = (const float*)d_in[20];
    const float* A_b       = (const float*)d_in[21];
    const float* A_v       = (const float*)d_in[22];
    const float* out_w     = (const float*)d_in[23];
    const float* out_b     = (const float*)d_in[24];

    void *p_esrc, *p_etgt, *p_gxf, *p_gxb, *p_gxemb, *p_srchid, *p_Uh, *p_P, *p_decout, *p_wbf, *p_abf, *p_zb;
    cudaGetSymbolAddress(&p_esrc, g_esrc);
    cudaGetSymbolAddress(&p_etgt, g_etgt);
    cudaGetSymbolAddress(&p_gxf, g_gxf);
    cudaGetSymbolAddress(&p_gxb, g_gxb);
    cudaGetSymbolAddress(&p_gxemb, g_gxemb);
    cudaGetSymbolAddress(&p_srchid, g_srchid);
    cudaGetSymbolAddress(&p_Uh, g_Uh);
    cudaGetSymbolAddress(&p_P, g_P);
    cudaGetSymbolAddress(&p_decout, g_decout);
    cudaGetSymbolAddress(&p_wbf, g_wbf);
    cudaGetSymbolAddress(&p_abf, g_abf);
    cudaGetSymbolAddress(&p_zb, g_zb);

    const int enc_smem = (3072 + 4096) * 16;   // 114688 B
    const int dec_smem = (2048 + 4096) * 16;   // 98304 B
    cudaFuncSetAttribute(enc_persist, cudaFuncAttributeMaxDynamicSharedMemorySize, enc_smem);
    cudaFuncSetAttribute(dec_persist, cudaFuncAttributeMaxDynamicSharedMemorySize, dec_smem);

    zero_h_kernel<<<(H * B + 255) / 256, 256>>>();
    embed_kernel<<<B * S + B * T, 128>>>(src_seqs, tgt_seqs, src_emb, tgt_emb);

    gemm_nt<1><<<dim3(G3 / GBN, (B * S) / GBM), 256>>>(
        (const float*)p_esrc, E, enc_Wih_f, E, enc_bih_f, (float*)p_gxf, G3, E, S);
    gemm_nt<1><<<dim3(G3 / GBN, (B * S) / GBM), 256>>>(
        (const float*)p_esrc, E, enc_Wih_b, E, enc_bih_b, (float*)p_gxb, G3, E, S);
    gemm_nt<1><<<dim3(G3 / GBN, (B * T) / GBM), 256>>>(
        (const float*)p_etgt, E, dec_Wih, G3, dec_bih, (float*)p_gxemb, G3, E, T);

    enc_persist<<<ENC_BLOCKS, 128, enc_smem>>>(enc_Whh_f, enc_bhh_f, enc_Whh_b, enc_bhh_b, src_lengths);

    gemm_nt<0><<<dim3(H / GBN, (B * S) / GBM), 256>>>(
        (const float*)p_srchid, 2 * H, U_w, 2 * H, U_b, (float*)p_Uh, H, 2 * H, S);
    // P = srchid @ Wih_c^T   -> [b][j][s]
    gemm_nt<2><<<dim3(G3 / GBN, (B * S) / GBM), 256>>>(
        (const float*)p_srchid, 2 * H, dec_Wih + 512, G3, (const float*)p_zb, (float*)p_P, 0, 2 * H, S);

    dec_persist<<<DEC_BLOCKS, 128, dec_smem>>>(dec_Whh, dec_bhh, A_W, A_b, A_v,
                                               src_lengths, tgt_lengths);

    cvt_bf16<<<(B * T * H / 8 + 255) / 256, 256>>>((const float*)p_decout,
                                                   (__nv_bfloat16*)p_abf, B * T * H / 8);
    cvt_bf16<<<((int)((size_t)V * H / 8) + 255) / 256, 256>>>(out_w,
                                                   (__nv_bfloat16*)p_wbf, (int)((size_t)V * H / 8));

    gemm_logits<<<dim3(V / LBN, (B * T) / LBM), 256>>>(out_b);
    merge_lse<<<B * T, 256>>>(tgt_seqs, out_b);
    final_loss<<<1, 256>>>(tgt_seqs, (float*)d_out);
}